// round 2
// baseline (speedup 1.0000x reference)
#include <cuda_runtime.h>
#include <cuda_bf16.h>
#include <stdint.h>
#include <math.h>

// ---------------------------------------------------------------------------
// MomentumAttention (linear attention):
//   Qf = (elu(Q)+1)*scale ; Kf = (elu(K)+1)*mask*scale*mw[l] ; Vf = V*mask
//   KV[d][e] = sum_l Kf[l][d]*Vf[l][e] ;  X = Qf @ KV
//   mw[l] = (1 - MU^(L-l))/(1-MU)  (0-based l), scale = L^-0.25
// bf16 hi/lo split (3 MMAs, drop lo*lo) for <= ~2e-5 rel err.
// ---------------------------------------------------------------------------

#define LLc 8192
#define DDc 128
#define BHc 32
#define CHUNKSc 16
#define CLc (LLc / CHUNKSc)   // 512

// scratch (allocation-free rule: __device__ globals)
__device__ float    g_KVp[CHUNKSc * BHc * DDc * DDc];  // 33.5 MB partials
__device__ float    g_kw[LLc];
__device__ uint32_t g_KVThi[BHc * DDc * (DDc / 2)];    // [bh][e][dword]
__device__ uint32_t g_KVTlo[BHc * DDc * (DDc / 2)];

__device__ __forceinline__ float elup(float x) {
  return x > 0.0f ? x + 1.0f : __expf(x);
}

// pack two floats -> bf16 hi pair + bf16 residual pair (low half = first elem)
__device__ __forceinline__ void split_pair(float a, float b,
                                           uint32_t& hi, uint32_t& lo) {
  __nv_bfloat16 ha = __float2bfloat16_rn(a);
  __nv_bfloat16 hb = __float2bfloat16_rn(b);
  hi = ((uint32_t)__bfloat16_as_ushort(hb) << 16) |
       (uint32_t)__bfloat16_as_ushort(ha);
  __nv_bfloat16 la = __float2bfloat16_rn(a - __bfloat162float(ha));
  __nv_bfloat16 lb = __float2bfloat16_rn(b - __bfloat162float(hb));
  lo = ((uint32_t)__bfloat16_as_ushort(lb) << 16) |
       (uint32_t)__bfloat16_as_ushort(la);
}

__device__ __forceinline__ void mma_bf16(float* c, const uint32_t* a,
                                         const uint32_t* b) {
  asm volatile(
      "mma.sync.aligned.m16n8k16.row.col.f32.bf16.bf16.f32 "
      "{%0,%1,%2,%3},{%4,%5,%6,%7},{%8,%9},{%0,%1,%2,%3};\n"
      : "+f"(c[0]), "+f"(c[1]), "+f"(c[2]), "+f"(c[3])
      : "r"(a[0]), "r"(a[1]), "r"(a[2]), "r"(a[3]), "r"(b[0]), "r"(b[1]));
}

// ---------------------------------------------------------------------------
__global__ void ma_init(float scale) {
  int l = blockIdx.x * blockDim.x + threadIdx.x;
  if (l < LLc) {
    float p = powf(0.9f, (float)(LLc - l));
    g_kw[l] = scale * (1.0f - p) / (1.0f - 0.9f);
  }
}

// ---------------------------------------------------------------------------
// Pass 1: per (chunk, bh) CTA: C[d][e] += sum_{l in chunk} Kf[l][d]*Vf[l][e]
// A = Kf^T in smem [d][l-words], B = Vf^T in smem [e][l-words]; rows padded
// to 18 words (72B). 8 warps, each owns a 32(m) x 64(n) slab of the 128x128 C.
// ---------------------------------------------------------------------------
__global__ void __launch_bounds__(256) ma_pass1(const float* __restrict__ Kg_,
                                                const float* __restrict__ Vg_,
                                                const float* __restrict__ Mg_) {
  extern __shared__ uint32_t sm[];
  uint32_t* sKhi = sm;
  uint32_t* sKlo = sm + 2304;
  uint32_t* sVhi = sm + 4608;
  uint32_t* sVlo = sm + 6912;

  const int tid = threadIdx.x;
  const int bh = blockIdx.y;
  const int b = bh >> 4;
  const int chunk = blockIdx.x;
  const float* Kg = Kg_ + (size_t)bh * LLc * DDc;
  const float* Vg = Vg_ + (size_t)bh * LLc * DDc;
  const float* Mg = Mg_ + (size_t)b * LLc;

  const int warp = tid >> 5, lane = tid & 31;
  const int g = lane >> 2, t = lane & 3;
  const int mo = (warp & 3) * 32;     // d offset
  const int no = (warp >> 2) * 64;    // e offset
  const int dst = tid & 127;          // staging row (d for K, e for V)
  const int lp0 = tid >> 7;           // 0 or 1

  float C[2][8][4];
#pragma unroll
  for (int i = 0; i < 2; i++)
#pragma unroll
    for (int j = 0; j < 8; j++)
#pragma unroll
      for (int q = 0; q < 4; q++) C[i][j][q] = 0.0f;

  const int l0c = chunk * CLc;
  for (int step = 0; step < CLc / 32; ++step) {
    const int l0 = l0c + step * 32;
    __syncthreads();
    // ---- stage 32 l's, transposed, bf16 hi/lo ----
    for (int lp = lp0; lp < 16; lp += 2) {
      int l = l0 + lp * 2;
      float m0 = Mg[l], m1 = Mg[l + 1];
      float w0 = g_kw[l] * m0, w1 = g_kw[l + 1] * m1;
      float f0 = elup(Kg[(size_t)l * DDc + dst]) * w0;
      float f1 = elup(Kg[(size_t)(l + 1) * DDc + dst]) * w1;
      uint32_t hi, lo;
      split_pair(f0, f1, hi, lo);
      sKhi[dst * 18 + lp] = hi;
      sKlo[dst * 18 + lp] = lo;
      float v0 = Vg[(size_t)l * DDc + dst] * m0;
      float v1 = Vg[(size_t)(l + 1) * DDc + dst] * m1;
      split_pair(v0, v1, hi, lo);
      sVhi[dst * 18 + lp] = hi;
      sVlo[dst * 18 + lp] = lo;
    }
    __syncthreads();
    // ---- MMA: two k16 sub-steps ----
#pragma unroll
    for (int kk = 0; kk < 2; ++kk) {
      const int wk = kk * 8;
      uint32_t Ahi[2][4], Alo[2][4];
#pragma unroll
      for (int mt = 0; mt < 2; ++mt) {
        int r0 = (mo + mt * 16 + g) * 18 + wk + t;
        int r1 = (mo + mt * 16 + g + 8) * 18 + wk + t;
        Ahi[mt][0] = sKhi[r0]; Ahi[mt][1] = sKhi[r1];
        Ahi[mt][2] = sKhi[r0 + 4]; Ahi[mt][3] = sKhi[r1 + 4];
        Alo[mt][0] = sKlo[r0]; Alo[mt][1] = sKlo[r1];
        Alo[mt][2] = sKlo[r0 + 4]; Alo[mt][3] = sKlo[r1 + 4];
      }
#pragma unroll
      for (int nt = 0; nt < 8; ++nt) {
        int rb = (no + nt * 8 + g) * 18 + wk + t;
        uint32_t Bhi[2] = {sVhi[rb], sVhi[rb + 4]};
        uint32_t Blo[2] = {sVlo[rb], sVlo[rb + 4]};
#pragma unroll
        for (int mt = 0; mt < 2; ++mt) {
          mma_bf16(C[mt][nt], Ahi[mt], Bhi);
          mma_bf16(C[mt][nt], Ahi[mt], Blo);
          mma_bf16(C[mt][nt], Alo[mt], Bhi);
        }
      }
    }
  }
  // ---- epilogue: write per-chunk partial ----
  float* out = g_KVp + (size_t)(chunk * BHc + bh) * DDc * DDc;
#pragma unroll
  for (int mt = 0; mt < 2; ++mt)
#pragma unroll
    for (int nt = 0; nt < 8; ++nt) {
      int d0 = mo + mt * 16 + g;
      int e0 = no + nt * 8 + t * 2;
      *reinterpret_cast<float2*>(out + (size_t)d0 * DDc + e0) =
          make_float2(C[mt][nt][0], C[mt][nt][1]);
      *reinterpret_cast<float2*>(out + (size_t)(d0 + 8) * DDc + e0) =
          make_float2(C[mt][nt][2], C[mt][nt][3]);
    }
}

// ---------------------------------------------------------------------------
// Reduce partials -> KVT[bh][e][d] as packed bf16 hi/lo (pairs along d).
// ---------------------------------------------------------------------------
__global__ void __launch_bounds__(128) ma_reduce() {
  const int e = threadIdx.x;
  const int bh = blockIdx.x >> 6;
  const int dp = blockIdx.x & 63;
  const int d = dp * 2;
  float a0 = 0.0f, a1 = 0.0f;
  for (int c = 0; c < CHUNKSc; ++c) {
    const float* p = g_KVp + (size_t)(c * BHc + bh) * DDc * DDc;
    a0 += p[(size_t)d * DDc + e];
    a1 += p[(size_t)(d + 1) * DDc + e];
  }
  uint32_t hi, lo;
  split_pair(a0, a1, hi, lo);
  g_KVThi[(size_t)bh * 8192 + e * 64 + dp] = hi;
  g_KVTlo[(size_t)bh * 8192 + e * 64 + dp] = lo;
}

// ---------------------------------------------------------------------------
// Pass 2: X[l][e] = Qf[l][:] @ KV[:][e].  KVT resident in smem (rows padded
// to 66 words), Q staged in 4 slices of 32 d. Same warp tiling as pass 1.
// ---------------------------------------------------------------------------
__global__ void __launch_bounds__(256) ma_pass2(const float* __restrict__ Qg_,
                                                float* __restrict__ Xg_,
                                                float scale) {
  extern __shared__ uint32_t sm[];
  uint32_t* sBhi = sm;            // 128*66
  uint32_t* sBlo = sm + 8448;
  uint32_t* sQhi = sm + 16896;    // 128*18
  uint32_t* sQlo = sm + 19200;

  const int tid = threadIdx.x;
  const int bh = blockIdx.y;
  const int l0 = blockIdx.x * 128;
  const float* Qg = Qg_ + (size_t)bh * LLc * DDc;
  float* Xg = Xg_ + (size_t)bh * LLc * DDc;

  const int warp = tid >> 5, lane = tid & 31;
  const int g = lane >> 2, t = lane & 3;
  const int mo = (warp & 3) * 32;   // l offset
  const int no = (warp >> 2) * 64;  // e offset

  {
    const uint32_t* shi = g_KVThi + (size_t)bh * 8192;
    const uint32_t* slo = g_KVTlo + (size_t)bh * 8192;
    for (int idx = tid; idx < 8192; idx += 256) {
      int e = idx >> 6, w = idx & 63;
      sBhi[e * 66 + w] = shi[idx];
      sBlo[e * 66 + w] = slo[idx];
    }
  }

  float C[2][8][4];
#pragma unroll
  for (int i = 0; i < 2; i++)
#pragma unroll
    for (int j = 0; j < 8; j++)
#pragma unroll
      for (int q = 0; q < 4; q++) C[i][j][q] = 0.0f;

  for (int s = 0; s < 4; ++s) {
    __syncthreads();
    // stage Q slice [128 l][32 d] hi/lo
    for (int idx = tid; idx < 2048; idx += 256) {
      int l = idx >> 4, w = idx & 15;
      float2 q = *reinterpret_cast<const float2*>(
          Qg + (size_t)(l0 + l) * DDc + s * 32 + w * 2);
      float f0 = elup(q.x) * scale;
      float f1 = elup(q.y) * scale;
      uint32_t hi, lo;
      split_pair(f0, f1, hi, lo);
      sQhi[l * 18 + w] = hi;
      sQlo[l * 18 + w] = lo;
    }
    __syncthreads();
#pragma unroll
    for (int kk = 0; kk < 2; ++kk) {
      const int wq = kk * 8;
      const int wb = s * 16 + kk * 8;
      uint32_t Ahi[2][4], Alo[2][4];
#pragma unroll
      for (int mt = 0; mt < 2; ++mt) {
        int r0 = (mo + mt * 16 + g) * 18 + wq + t;
        int r1 = (mo + mt * 16 + g + 8) * 18 + wq + t;
        Ahi[mt][0] = sQhi[r0]; Ahi[mt][1] = sQhi[r1];
        Ahi[mt][2] = sQhi[r0 + 4]; Ahi[mt][3] = sQhi[r1 + 4];
        Alo[mt][0] = sQlo[r0]; Alo[mt][1] = sQlo[r1];
        Alo[mt][2] = sQlo[r0 + 4]; Alo[mt][3] = sQlo[r1 + 4];
      }
#pragma unroll
      for (int nt = 0; nt < 8; ++nt) {
        int rb = (no + nt * 8 + g) * 66 + wb + t;
        uint32_t Bhi[2] = {sBhi[rb], sBhi[rb + 4]};
        uint32_t Blo[2] = {sBlo[rb], sBlo[rb + 4]};
#pragma unroll
        for (int mt = 0; mt < 2; ++mt) {
          mma_bf16(C[mt][nt], Ahi[mt], Bhi);
          mma_bf16(C[mt][nt], Ahi[mt], Blo);
          mma_bf16(C[mt][nt], Alo[mt], Bhi);
        }
      }
    }
  }
  // epilogue
#pragma unroll
  for (int mt = 0; mt < 2; ++mt)
#pragma unroll
    for (int nt = 0; nt < 8; ++nt) {
      int lr = l0 + mo + mt * 16 + g;
      int e0 = no + nt * 8 + t * 2;
      *reinterpret_cast<float2*>(Xg + (size_t)lr * DDc + e0) =
          make_float2(C[mt][nt][0], C[mt][nt][1]);
      *reinterpret_cast<float2*>(Xg + (size_t)(lr + 8) * DDc + e0) =
          make_float2(C[mt][nt][2], C[mt][nt][3]);
    }
}

// ---------------------------------------------------------------------------
extern "C" void kernel_launch(void* const* d_in, const int* in_sizes, int n_in,
                              void* d_out, int out_size) {
  const float* Q = (const float*)d_in[0];
  const float* K = (const float*)d_in[1];
  const float* V = (const float*)d_in[2];
  const float* M = (const float*)d_in[3];
  float* X = (float*)d_out;
  (void)in_sizes; (void)n_in; (void)out_size;

  const float scale = powf((float)LLc, -0.25f);

  cudaFuncSetAttribute(ma_pass2, cudaFuncAttributeMaxDynamicSharedMemorySize,
                       86016);

  ma_init<<<LLc / 256, 256>>>(scale);
  dim3 g1(CHUNKSc, BHc);
  ma_pass1<<<g1, 256, 36864>>>(K, V, M);
  ma_reduce<<<BHc * 64, 128>>>();
  dim3 g2(LLc / 128, BHc);
  ma_pass2<<<g2, 256, 86016>>>(Q, X, scale);
}

// round 3
// speedup vs baseline: 1.3923x; 1.3923x over previous
#include <cuda_runtime.h>
#include <cuda_bf16.h>
#include <stdint.h>
#include <math.h>

// ---------------------------------------------------------------------------
// MomentumAttention (linear attention), bf16 hi/lo split (3-term MMA):
//   Qf = (elu(Q)+1)*scale ; Kf = (elu(K)+1)*mask*scale*mw[l] ; Vf = V*mask
//   KV[d][e] = sum_l Kf[l][d]*Vf[l][e] ;  X = Qf @ KV
// ---------------------------------------------------------------------------

#define LLc 8192
#define DDc 128
#define BHc 32
#define CHUNKSc 16
#define CLc (LLc / CHUNKSc)   // 512

__device__ float    g_KVp[CHUNKSc * BHc * DDc * DDc];  // per-chunk partials
__device__ float    g_kwm[2 * LLc];                    // scale*mw*mask per (b,l)
__device__ uint32_t g_KVThi[BHc * DDc * (DDc / 2)];    // [bh][e][d-pair]
__device__ uint32_t g_KVTlo[BHc * DDc * (DDc / 2)];

__device__ __forceinline__ float elup(float x) {
  return x > 0.0f ? x + 1.0f : __expf(x);
}

__device__ __forceinline__ void split_pair(float a, float b,
                                           uint32_t& hi, uint32_t& lo) {
  __nv_bfloat162 h = __floats2bfloat162_rn(a, b);
  hi = *reinterpret_cast<uint32_t*>(&h);
  float ra = a - __bfloat162float(h.x);
  float rb = b - __bfloat162float(h.y);
  __nv_bfloat162 l2 = __floats2bfloat162_rn(ra, rb);
  lo = *reinterpret_cast<uint32_t*>(&l2);
}

__device__ __forceinline__ void mma_bf16(float* c, const uint32_t* a,
                                         const uint32_t* b) {
  asm volatile(
      "mma.sync.aligned.m16n8k16.row.col.f32.bf16.bf16.f32 "
      "{%0,%1,%2,%3},{%4,%5,%6,%7},{%8,%9},{%0,%1,%2,%3};\n"
      : "+f"(c[0]), "+f"(c[1]), "+f"(c[2]), "+f"(c[3])
      : "r"(a[0]), "r"(a[1]), "r"(a[2]), "r"(a[3]), "r"(b[0]), "r"(b[1]));
}

__device__ __forceinline__ void ldsm_x4(uint32_t* r, uint32_t addr) {
  asm volatile(
      "ldmatrix.sync.aligned.m8n8.x4.shared.b16 {%0,%1,%2,%3}, [%4];"
      : "=r"(r[0]), "=r"(r[1]), "=r"(r[2]), "=r"(r[3])
      : "r"(addr));
}

// ---------------------------------------------------------------------------
__global__ void ma_init(const float* __restrict__ mask, float scale) {
  int idx = blockIdx.x * blockDim.x + threadIdx.x;   // 0 .. 2*LLc-1
  if (idx < 2 * LLc) {
    int l = idx & (LLc - 1);
    float p = powf(0.9f, (float)(LLc - l));
    g_kwm[idx] = scale * (1.0f - p) * 10.0f * mask[idx];
  }
}

// ---------------------------------------------------------------------------
// Pass 1: per (chunk, bh): C[d][e] += sum_l Kf[l][d]*Vf[l][e]
// smem: Kf^T / Vf^T as bf16 hi/lo, rows(d or e) of 32 words (64 l), XOR-chunk
// swizzled. 8 warps, warp tile 32(d) x 64(e). ldmatrix fragments.
// ---------------------------------------------------------------------------
__global__ void __launch_bounds__(256, 2)
ma_pass1(const float* __restrict__ Kin, const float* __restrict__ Vin,
         const float* __restrict__ mask) {
  extern __shared__ uint32_t sm[];
  const int OFF_KHI = 0, OFF_KLO = 4096, OFF_VHI = 8192, OFF_VLO = 12288;

  const int tid = threadIdx.x;
  const int bh = blockIdx.y;
  const int b = bh >> 4;
  const int chunk = blockIdx.x;
  const float* Kg = Kin + (size_t)bh * LLc * DDc;
  const float* Vg = Vin + (size_t)bh * LLc * DDc;
  const float* Mg = mask + (size_t)b * LLc;
  const float* Wg = g_kwm + (size_t)b * LLc;

  const int warp = tid >> 5, lane = tid & 31;
  const int g = lane >> 2, t = lane & 3;
  const int q = lane >> 3, r8 = lane & 7;
  const int qh = q >> 1, ql = q & 1;
  const int mo = (warp & 3) * 32;    // d
  const int no = (warp >> 2) * 64;   // e

  uint32_t smb = (uint32_t)__cvta_generic_to_shared(sm);

  uint32_t aBhi[2], aBlo[2];
#pragma unroll
  for (int mt = 0; mt < 2; ++mt) {
    int row = mo + mt * 16 + ql * 8 + r8;
    aBhi[mt] = smb + (OFF_KHI + row * 32) * 4;
    aBlo[mt] = smb + (OFF_KLO + row * 32) * 4;
  }
  uint32_t bBhi[4], bBlo[4];
#pragma unroll
  for (int np = 0; np < 4; ++np) {
    int row = no + np * 16 + qh * 8 + r8;
    bBhi[np] = smb + (OFF_VHI + row * 32) * 4;
    bBlo[np] = smb + (OFF_VLO + row * 32) * 4;
  }

  const int dst = tid & 127;
  const int jb = (tid >> 7) * 4;
  const int swk = dst & 7;

  float C[2][8][4];
#pragma unroll
  for (int i = 0; i < 2; i++)
#pragma unroll
    for (int j = 0; j < 8; j++)
#pragma unroll
      for (int p = 0; p < 4; p++) C[i][j][p] = 0.0f;

  const int l0c = chunk * CLc;
  for (int step = 0; step < CLc / 64; ++step) {
    const int l0 = l0c + step * 64;
    __syncthreads();
    // ---- stage 64 l (8 chunks of 8 l), transposed, bf16 hi/lo ----
#pragma unroll
    for (int j = jb; j < jb + 4; ++j) {
      int l = l0 + j * 8;
      float kf[8], vf[8];
#pragma unroll
      for (int i = 0; i < 8; i += 2) {
        float2 w2 = *reinterpret_cast<const float2*>(Wg + l + i);
        float2 m2 = *reinterpret_cast<const float2*>(Mg + l + i);
        float k0 = Kg[(size_t)(l + i) * DDc + dst];
        float k1 = Kg[(size_t)(l + i + 1) * DDc + dst];
        float v0 = Vg[(size_t)(l + i) * DDc + dst];
        float v1 = Vg[(size_t)(l + i + 1) * DDc + dst];
        kf[i] = elup(k0) * w2.x;
        kf[i + 1] = elup(k1) * w2.y;
        vf[i] = v0 * m2.x;
        vf[i + 1] = v1 * m2.y;
      }
      uint4 khi, klo, vhi, vlo;
      split_pair(kf[0], kf[1], khi.x, klo.x);
      split_pair(kf[2], kf[3], khi.y, klo.y);
      split_pair(kf[4], kf[5], khi.z, klo.z);
      split_pair(kf[6], kf[7], khi.w, klo.w);
      split_pair(vf[0], vf[1], vhi.x, vlo.x);
      split_pair(vf[2], vf[3], vhi.y, vlo.y);
      split_pair(vf[4], vf[5], vhi.z, vlo.z);
      split_pair(vf[6], vf[7], vhi.w, vlo.w);
      int off = dst * 32 + ((j ^ swk) << 2);
      *reinterpret_cast<uint4*>(sm + OFF_KHI + off) = khi;
      *reinterpret_cast<uint4*>(sm + OFF_KLO + off) = klo;
      *reinterpret_cast<uint4*>(sm + OFF_VHI + off) = vhi;
      *reinterpret_cast<uint4*>(sm + OFF_VLO + off) = vlo;
    }
    __syncthreads();
    // ---- MMA: 4 k16 sub-steps ----
#pragma unroll
    for (int kk = 0; kk < 4; ++kk) {
      uint32_t Ahi[2][4], Alo[2][4];
      int offA = (((kk * 2 + qh) ^ r8) << 4);
      ldsm_x4(Ahi[0], aBhi[0] + offA);
      ldsm_x4(Alo[0], aBlo[0] + offA);
      ldsm_x4(Ahi[1], aBhi[1] + offA);
      ldsm_x4(Alo[1], aBlo[1] + offA);
      int offB = (((kk * 2 + ql) ^ r8) << 4);
#pragma unroll
      for (int np = 0; np < 4; ++np) {
        uint32_t Bh[4], Bl[4];
        ldsm_x4(Bh, bBhi[np] + offB);
        ldsm_x4(Bl, bBlo[np] + offB);
#pragma unroll
        for (int mt = 0; mt < 2; ++mt) {
          mma_bf16(C[mt][2 * np], Ahi[mt], Bh);
          mma_bf16(C[mt][2 * np], Ahi[mt], Bl);
          mma_bf16(C[mt][2 * np], Alo[mt], Bh);
          mma_bf16(C[mt][2 * np + 1], Ahi[mt], Bh + 2);
          mma_bf16(C[mt][2 * np + 1], Ahi[mt], Bl + 2);
          mma_bf16(C[mt][2 * np + 1], Alo[mt], Bh + 2);
        }
      }
    }
  }
  // ---- epilogue: per-chunk partial ----
  float* out = g_KVp + (size_t)(chunk * BHc + bh) * DDc * DDc;
#pragma unroll
  for (int mt = 0; mt < 2; ++mt)
#pragma unroll
    for (int nt = 0; nt < 8; ++nt) {
      int d0 = mo + mt * 16 + g;
      int e0 = no + nt * 8 + t * 2;
      *reinterpret_cast<float2*>(out + (size_t)d0 * DDc + e0) =
          make_float2(C[mt][nt][0], C[mt][nt][1]);
      *reinterpret_cast<float2*>(out + (size_t)(d0 + 8) * DDc + e0) =
          make_float2(C[mt][nt][2], C[mt][nt][3]);
    }
}

// ---------------------------------------------------------------------------
// Reduce partials -> KVT[bh][e][d-pair] packed bf16 hi/lo.
// ---------------------------------------------------------------------------
__global__ void __launch_bounds__(128) ma_reduce() {
  const int e = threadIdx.x;
  const int bh = blockIdx.x >> 6;
  const int dp = blockIdx.x & 63;
  const int d = dp * 2;
  float a0 = 0.0f, a1 = 0.0f;
  for (int c = 0; c < CHUNKSc; ++c) {
    const float* p = g_KVp + (size_t)(c * BHc + bh) * DDc * DDc;
    a0 += p[(size_t)d * DDc + e];
    a1 += p[(size_t)(d + 1) * DDc + e];
  }
  uint32_t hi, lo;
  split_pair(a0, a1, hi, lo);
  g_KVThi[(size_t)bh * 8192 + e * 64 + dp] = hi;
  g_KVTlo[(size_t)bh * 8192 + e * 64 + dp] = lo;
}

// ---------------------------------------------------------------------------
// Pass 2: X[l][e] = Qf[l][:] @ KV[:][e]. B (KV^T) smem-resident (XOR-swizzled,
// 64-word rows), A (Q) loaded directly from gmem into fragments. No main-loop
// syncs. 8 warps, warp tile 32(l) x 64(e).
// ---------------------------------------------------------------------------
__global__ void __launch_bounds__(256, 2)
ma_pass2(const float* __restrict__ Qin, float* __restrict__ Xout, float scale) {
  extern __shared__ uint32_t sm[];
  const int OFF_BHI = 0, OFF_BLO = 8192;

  const int tid = threadIdx.x;
  const int bh = blockIdx.y;
  const int l0 = blockIdx.x * 128;
  const float* Qg = Qin + (size_t)bh * LLc * DDc;
  float* Xg = Xout + (size_t)bh * LLc * DDc;

  const int warp = tid >> 5, lane = tid & 31;
  const int g = lane >> 2, t = lane & 3;
  const int q = lane >> 3, r8 = lane & 7;
  const int qh = q >> 1, ql = q & 1;
  const int mo = (warp & 3) * 32;   // l
  const int no = (warp >> 2) * 64;  // e

  uint32_t smb = (uint32_t)__cvta_generic_to_shared(sm);

  // ---- stage B once (swizzled) ----
  {
    const uint4* shi = reinterpret_cast<const uint4*>(g_KVThi + (size_t)bh * 8192);
    const uint4* slo = reinterpret_cast<const uint4*>(g_KVTlo + (size_t)bh * 8192);
#pragma unroll
    for (int k = 0; k < 8; ++k) {
      int idx4 = tid + k * 256;        // 0..2047
      int e = idx4 >> 4, c = idx4 & 15;
      int w = e * 64 + ((c ^ (e & 7)) << 2);
      *reinterpret_cast<uint4*>(sm + OFF_BHI + w) = shi[idx4];
      *reinterpret_cast<uint4*>(sm + OFF_BLO + w) = slo[idx4];
    }
  }

  uint32_t bBhi[4], bBlo[4];
#pragma unroll
  for (int np = 0; np < 4; ++np) {
    int row = no + np * 16 + qh * 8 + r8;
    bBhi[np] = smb + (OFF_BHI + row * 64) * 4;
    bBlo[np] = smb + (OFF_BLO + row * 64) * 4;
  }

  const float2* Qp[2];
  const float2* Qp8[2];
#pragma unroll
  for (int mt = 0; mt < 2; ++mt) {
    int row = l0 + mo + mt * 16 + g;
    Qp[mt] = reinterpret_cast<const float2*>(Qg + (size_t)row * DDc);
    Qp8[mt] = Qp[mt] + 8 * (DDc / 2);
  }

  float C[2][8][4];
#pragma unroll
  for (int i = 0; i < 2; i++)
#pragma unroll
    for (int j = 0; j < 8; j++)
#pragma unroll
      for (int p = 0; p < 4; p++) C[i][j][p] = 0.0f;

  __syncthreads();

#pragma unroll 2
  for (int kk = 0; kk < 8; ++kk) {
    uint32_t Ahi[2][4], Alo[2][4];
#pragma unroll
    for (int mt = 0; mt < 2; ++mt) {
      float2 q00 = Qp[mt][kk * 8 + t];
      float2 q01 = Qp[mt][kk * 8 + t + 4];
      float2 q10 = Qp8[mt][kk * 8 + t];
      float2 q11 = Qp8[mt][kk * 8 + t + 4];
      split_pair(elup(q00.x) * scale, elup(q00.y) * scale, Ahi[mt][0], Alo[mt][0]);
      split_pair(elup(q10.x) * scale, elup(q10.y) * scale, Ahi[mt][1], Alo[mt][1]);
      split_pair(elup(q01.x) * scale, elup(q01.y) * scale, Ahi[mt][2], Alo[mt][2]);
      split_pair(elup(q11.x) * scale, elup(q11.y) * scale, Ahi[mt][3], Alo[mt][3]);
    }
    int offB = (((kk * 2 + ql) ^ r8) << 4);
#pragma unroll
    for (int np = 0; np < 4; ++np) {
      uint32_t Bh[4], Bl[4];
      ldsm_x4(Bh, bBhi[np] + offB);
      ldsm_x4(Bl, bBlo[np] + offB);
#pragma unroll
      for (int mt = 0; mt < 2; ++mt) {
        mma_bf16(C[mt][2 * np], Ahi[mt], Bh);
        mma_bf16(C[mt][2 * np], Ahi[mt], Bl);
        mma_bf16(C[mt][2 * np], Alo[mt], Bh);
        mma_bf16(C[mt][2 * np + 1], Ahi[mt], Bh + 2);
        mma_bf16(C[mt][2 * np + 1], Ahi[mt], Bl + 2);
        mma_bf16(C[mt][2 * np + 1], Alo[mt], Bh + 2);
      }
    }
  }
  // ---- epilogue ----
#pragma unroll
  for (int mt = 0; mt < 2; ++mt)
#pragma unroll
    for (int nt = 0; nt < 8; ++nt) {
      int lr = l0 + mo + mt * 16 + g;
      int e0 = no + nt * 8 + t * 2;
      *reinterpret_cast<float2*>(Xg + (size_t)lr * DDc + e0) =
          make_float2(C[mt][nt][0], C[mt][nt][1]);
      *reinterpret_cast<float2*>(Xg + (size_t)(lr + 8) * DDc + e0) =
          make_float2(C[mt][nt][2], C[mt][nt][3]);
    }
}

// ---------------------------------------------------------------------------
extern "C" void kernel_launch(void* const* d_in, const int* in_sizes, int n_in,
                              void* d_out, int out_size) {
  const float* Q = (const float*)d_in[0];
  const float* K = (const float*)d_in[1];
  const float* V = (const float*)d_in[2];
  const float* M = (const float*)d_in[3];
  float* X = (float*)d_out;
  (void)in_sizes; (void)n_in; (void)out_size;

  const float scale = powf((float)LLc, -0.25f);

  cudaFuncSetAttribute(ma_pass1, cudaFuncAttributeMaxDynamicSharedMemorySize,
                       65536);
  cudaFuncSetAttribute(ma_pass2, cudaFuncAttributeMaxDynamicSharedMemorySize,
                       65536);

  ma_init<<<(2 * LLc + 255) / 256, 256>>>(M, scale);
  dim3 g1(CHUNKSc, BHc);
  ma_pass1<<<g1, 256, 65536>>>(K, V, M);
  ma_reduce<<<BHc * 64, 128>>>();
  dim3 g2(LLc / 128, BHc);
  ma_pass2<<<g2, 256, 65536>>>(Q, X, scale);
}

// round 5
// speedup vs baseline: 1.5112x; 1.0854x over previous
#include <cuda_runtime.h>
#include <cuda_bf16.h>
#include <stdint.h>
#include <math.h>

// ---------------------------------------------------------------------------
// MomentumAttention (linear attention), bf16 hi/lo split (3-term MMA):
//   Qf = (elu(Q)+1)*scale ; Kf = (elu(K)+1)*mask*scale*mw[l] ; Vf = V*mask
//   KV[d][e] = sum_l Kf[l][d]*Vf[l][e] ;  X = Qf @ KV
// Legacy mma.sync path (tcgen05 unavailable on this build target).
// ---------------------------------------------------------------------------

#define LLc 8192
#define DDc 128
#define BHc 32
#define CHUNKSc 16
#define CLc (LLc / CHUNKSc)   // 512

__device__ float    g_KVp[CHUNKSc * BHc * DDc * DDc];  // per-chunk partials
__device__ float    g_kwm[2 * LLc];                    // scale*mw*mask per (b,l)
__device__ uint32_t g_KVThi[BHc * DDc * (DDc / 2)];    // [bh][e][d-pair]
__device__ uint32_t g_KVTlo[BHc * DDc * (DDc / 2)];

__device__ __forceinline__ float elup(float x) {
  return x > 0.0f ? x + 1.0f : __expf(x);
}

__device__ __forceinline__ void split_pair(float a, float b,
                                           uint32_t& hi, uint32_t& lo) {
  __nv_bfloat162 h = __floats2bfloat162_rn(a, b);
  hi = *reinterpret_cast<uint32_t*>(&h);
  float ra = a - __bfloat162float(h.x);
  float rb = b - __bfloat162float(h.y);
  __nv_bfloat162 l2 = __floats2bfloat162_rn(ra, rb);
  lo = *reinterpret_cast<uint32_t*>(&l2);
}

__device__ __forceinline__ void mma_bf16(float* c, const uint32_t* a,
                                         const uint32_t* b) {
  asm volatile(
      "mma.sync.aligned.m16n8k16.row.col.f32.bf16.bf16.f32 "
      "{%0,%1,%2,%3},{%4,%5,%6,%7},{%8,%9},{%0,%1,%2,%3};\n"
      : "+f"(c[0]), "+f"(c[1]), "+f"(c[2]), "+f"(c[3])
      : "r"(a[0]), "r"(a[1]), "r"(a[2]), "r"(a[3]), "r"(b[0]), "r"(b[1]));
}

__device__ __forceinline__ void ldsm_x4(uint32_t* r, uint32_t addr) {
  asm volatile(
      "ldmatrix.sync.aligned.m8n8.x4.shared.b16 {%0,%1,%2,%3}, [%4];"
      : "=r"(r[0]), "=r"(r[1]), "=r"(r[2]), "=r"(r[3])
      : "r"(addr));
}

// ---------------------------------------------------------------------------
__global__ void ma_init(const float* __restrict__ mask, float scale) {
  int idx = blockIdx.x * blockDim.x + threadIdx.x;   // 0 .. 2*LLc-1
  if (idx < 2 * LLc) {
    int l = idx & (LLc - 1);
    float p = powf(0.9f, (float)(LLc - l));
    g_kwm[idx] = scale * (1.0f - p) * 10.0f * mask[idx];
  }
}

// ---------------------------------------------------------------------------
// Pass 1: per (chunk, bh): C[d][e] += sum_l Kf[l][d]*Vf[l][e]
// (unchanged from R3 — known good)
// ---------------------------------------------------------------------------
__global__ void __launch_bounds__(256, 2)
ma_pass1(const float* __restrict__ Kin, const float* __restrict__ Vin,
         const float* __restrict__ mask) {
  extern __shared__ uint32_t sm[];
  const int OFF_KHI = 0, OFF_KLO = 4096, OFF_VHI = 8192, OFF_VLO = 12288;

  const int tid = threadIdx.x;
  const int bh = blockIdx.y;
  const int b = bh >> 4;
  const int chunk = blockIdx.x;
  const float* Kg = Kin + (size_t)bh * LLc * DDc;
  const float* Vg = Vin + (size_t)bh * LLc * DDc;
  const float* Mg = mask + (size_t)b * LLc;
  const float* Wg = g_kwm + (size_t)b * LLc;

  const int warp = tid >> 5, lane = tid & 31;
  const int g = lane >> 2, t = lane & 3;
  const int q = lane >> 3, r8 = lane & 7;
  const int qh = q >> 1, ql = q & 1;
  const int mo = (warp & 3) * 32;    // d
  const int no = (warp >> 2) * 64;   // e

  uint32_t smb = (uint32_t)__cvta_generic_to_shared(sm);

  uint32_t aBhi[2], aBlo[2];
#pragma unroll
  for (int mt = 0; mt < 2; ++mt) {
    int row = mo + mt * 16 + ql * 8 + r8;
    aBhi[mt] = smb + (OFF_KHI + row * 32) * 4;
    aBlo[mt] = smb + (OFF_KLO + row * 32) * 4;
  }
  uint32_t bBhi[4], bBlo[4];
#pragma unroll
  for (int np = 0; np < 4; ++np) {
    int row = no + np * 16 + qh * 8 + r8;
    bBhi[np] = smb + (OFF_VHI + row * 32) * 4;
    bBlo[np] = smb + (OFF_VLO + row * 32) * 4;
  }

  const int dst = tid & 127;
  const int jb = (tid >> 7) * 4;
  const int swk = dst & 7;

  float C[2][8][4];
#pragma unroll
  for (int i = 0; i < 2; i++)
#pragma unroll
    for (int j = 0; j < 8; j++)
#pragma unroll
      for (int p = 0; p < 4; p++) C[i][j][p] = 0.0f;

  const int l0c = chunk * CLc;
  for (int step = 0; step < CLc / 64; ++step) {
    const int l0 = l0c + step * 64;
    __syncthreads();
#pragma unroll
    for (int j = jb; j < jb + 4; ++j) {
      int l = l0 + j * 8;
      float kf[8], vf[8];
#pragma unroll
      for (int i = 0; i < 8; i += 2) {
        float2 w2 = *reinterpret_cast<const float2*>(Wg + l + i);
        float2 m2 = *reinterpret_cast<const float2*>(Mg + l + i);
        float k0 = Kg[(size_t)(l + i) * DDc + dst];
        float k1 = Kg[(size_t)(l + i + 1) * DDc + dst];
        float v0 = Vg[(size_t)(l + i) * DDc + dst];
        float v1 = Vg[(size_t)(l + i + 1) * DDc + dst];
        kf[i] = elup(k0) * w2.x;
        kf[i + 1] = elup(k1) * w2.y;
        vf[i] = v0 * m2.x;
        vf[i + 1] = v1 * m2.y;
      }
      uint4 khi, klo, vhi, vlo;
      split_pair(kf[0], kf[1], khi.x, klo.x);
      split_pair(kf[2], kf[3], khi.y, klo.y);
      split_pair(kf[4], kf[5], khi.z, klo.z);
      split_pair(kf[6], kf[7], khi.w, klo.w);
      split_pair(vf[0], vf[1], vhi.x, vlo.x);
      split_pair(vf[2], vf[3], vhi.y, vlo.y);
      split_pair(vf[4], vf[5], vhi.z, vlo.z);
      split_pair(vf[6], vf[7], vhi.w, vlo.w);
      int off = dst * 32 + ((j ^ swk) << 2);
      *reinterpret_cast<uint4*>(sm + OFF_KHI + off) = khi;
      *reinterpret_cast<uint4*>(sm + OFF_KLO + off) = klo;
      *reinterpret_cast<uint4*>(sm + OFF_VHI + off) = vhi;
      *reinterpret_cast<uint4*>(sm + OFF_VLO + off) = vlo;
    }
    __syncthreads();
#pragma unroll
    for (int kk = 0; kk < 4; ++kk) {
      uint32_t Ahi[2][4], Alo[2][4];
      int offA = (((kk * 2 + qh) ^ r8) << 4);
      ldsm_x4(Ahi[0], aBhi[0] + offA);
      ldsm_x4(Alo[0], aBlo[0] + offA);
      ldsm_x4(Ahi[1], aBhi[1] + offA);
      ldsm_x4(Alo[1], aBlo[1] + offA);
      int offB = (((kk * 2 + ql) ^ r8) << 4);
#pragma unroll
      for (int np = 0; np < 4; ++np) {
        uint32_t Bh[4], Bl[4];
        ldsm_x4(Bh, bBhi[np] + offB);
        ldsm_x4(Bl, bBlo[np] + offB);
#pragma unroll
        for (int mt = 0; mt < 2; ++mt) {
          mma_bf16(C[mt][2 * np], Ahi[mt], Bh);
          mma_bf16(C[mt][2 * np], Ahi[mt], Bl);
          mma_bf16(C[mt][2 * np], Alo[mt], Bh);
          mma_bf16(C[mt][2 * np + 1], Ahi[mt], Bh + 2);
          mma_bf16(C[mt][2 * np + 1], Ahi[mt], Bl + 2);
          mma_bf16(C[mt][2 * np + 1], Alo[mt], Bh + 2);
        }
      }
    }
  }
  float* out = g_KVp + (size_t)(chunk * BHc + bh) * DDc * DDc;
#pragma unroll
  for (int mt = 0; mt < 2; ++mt)
#pragma unroll
    for (int nt = 0; nt < 8; ++nt) {
      int d0 = mo + mt * 16 + g;
      int e0 = no + nt * 8 + t * 2;
      *reinterpret_cast<float2*>(out + (size_t)d0 * DDc + e0) =
          make_float2(C[mt][nt][0], C[mt][nt][1]);
      *reinterpret_cast<float2*>(out + (size_t)(d0 + 8) * DDc + e0) =
          make_float2(C[mt][nt][2], C[mt][nt][3]);
    }
}

// ---------------------------------------------------------------------------
__global__ void __launch_bounds__(128) ma_reduce() {
  const int e = threadIdx.x;
  const int bh = blockIdx.x >> 6;
  const int dp = blockIdx.x & 63;
  const int d = dp * 2;
  float a0 = 0.0f, a1 = 0.0f;
  for (int c = 0; c < CHUNKSc; ++c) {
    const float* p = g_KVp + (size_t)(c * BHc + bh) * DDc * DDc;
    a0 += p[(size_t)d * DDc + e];
    a1 += p[(size_t)(d + 1) * DDc + e];
  }
  uint32_t hi, lo;
  split_pair(a0, a1, hi, lo);
  g_KVThi[(size_t)bh * 8192 + e * 64 + dp] = hi;
  g_KVTlo[(size_t)bh * 8192 + e * 64 + dp] = lo;
}

// ---------------------------------------------------------------------------
// Pass 2 (e-split): CTA = (l-chunk of 128) x (bh, e-half of 64).
// B = KV^T e-half smem-resident (32 KB, XOR-swizzled 64-word rows).
// A (Q) loaded straight from gmem; warp tile 16 l x 64 e (unique l per warp).
// 3 CTAs/SM via __launch_bounds__(256,3).
// ---------------------------------------------------------------------------
__global__ void __launch_bounds__(256, 3)
ma_pass2(const float* __restrict__ Qin, float* __restrict__ Xout, float scale) {
  extern __shared__ uint32_t sm[];
  const int OFF_BHI = 0, OFF_BLO = 4096;

  const int tid = threadIdx.x;
  const int bh = blockIdx.y >> 1;
  const int eh = blockIdx.y & 1;
  const int l0 = blockIdx.x * 128;
  const float* Qg = Qin + (size_t)bh * LLc * DDc;
  float* Xg = Xout + (size_t)bh * LLc * DDc + eh * 64;

  const int warp = tid >> 5, lane = tid & 31;
  const int g = lane >> 2, t = lane & 3;
  const int q = lane >> 3, r8 = lane & 7;
  const int qh = q >> 1, ql = q & 1;
  const int lw = warp * 16;                 // warp's l offset (unique rows)

  uint32_t smb = (uint32_t)__cvta_generic_to_shared(sm);

  // ---- stage B e-half once (swizzled): 64 rows x 16 uint4 ----
  {
    const uint4* shi = reinterpret_cast<const uint4*>(
        g_KVThi + (size_t)bh * 8192 + (size_t)eh * 4096);
    const uint4* slo = reinterpret_cast<const uint4*>(
        g_KVTlo + (size_t)bh * 8192 + (size_t)eh * 4096);
#pragma unroll
    for (int i = 0; i < 4; ++i) {
      int idx4 = tid + i * 256;        // 0..1023
      int e = idx4 >> 4, c = idx4 & 15;
      int w = e * 64 + ((c ^ (e & 7)) << 2);
      *reinterpret_cast<uint4*>(sm + OFF_BHI + w) = shi[idx4];
      *reinterpret_cast<uint4*>(sm + OFF_BLO + w) = slo[idx4];
    }
  }

  uint32_t bBhi[4], bBlo[4];
#pragma unroll
  for (int np = 0; np < 4; ++np) {
    int row = np * 16 + qh * 8 + r8;
    bBhi[np] = smb + (OFF_BHI + row * 64) * 4;
    bBlo[np] = smb + (OFF_BLO + row * 64) * 4;
  }

  const float2* Qp =
      reinterpret_cast<const float2*>(Qg + (size_t)(l0 + lw + g) * DDc);
  const float2* Qp8 = Qp + 8 * (DDc / 2);

  float C[8][4];
#pragma unroll
  for (int j = 0; j < 8; j++)
#pragma unroll
    for (int p = 0; p < 4; p++) C[j][p] = 0.0f;

  __syncthreads();

#pragma unroll
  for (int kk = 0; kk < 8; ++kk) {
    float2 q00 = Qp[kk * 8 + t];
    float2 q01 = Qp[kk * 8 + t + 4];
    float2 q10 = Qp8[kk * 8 + t];
    float2 q11 = Qp8[kk * 8 + t + 4];
    uint32_t Ahi[4], Alo[4];
    split_pair(elup(q00.x) * scale, elup(q00.y) * scale, Ahi[0], Alo[0]);
    split_pair(elup(q10.x) * scale, elup(q10.y) * scale, Ahi[1], Alo[1]);
    split_pair(elup(q01.x) * scale, elup(q01.y) * scale, Ahi[2], Alo[2]);
    split_pair(elup(q11.x) * scale, elup(q11.y) * scale, Ahi[3], Alo[3]);
    int offB = (((kk * 2 + ql) ^ r8) << 4);
#pragma unroll
    for (int np = 0; np < 4; ++np) {
      uint32_t Bh[4], Bl[4];
      ldsm_x4(Bh, bBhi[np] + offB);
      ldsm_x4(Bl, bBlo[np] + offB);
      mma_bf16(C[2 * np], Ahi, Bh);
      mma_bf16(C[2 * np], Ahi, Bl);
      mma_bf16(C[2 * np], Alo, Bh);
      mma_bf16(C[2 * np + 1], Ahi, Bh + 2);
      mma_bf16(C[2 * np + 1], Ahi, Bl + 2);
      mma_bf16(C[2 * np + 1], Alo, Bh + 2);
    }
  }
  // ---- epilogue ----
#pragma unroll
  for (int nt = 0; nt < 8; ++nt) {
    int lr = l0 + lw + g;
    int e0 = nt * 8 + t * 2;
    *reinterpret_cast<float2*>(Xg + (size_t)lr * DDc + e0) =
        make_float2(C[nt][0], C[nt][1]);
    *reinterpret_cast<float2*>(Xg + (size_t)(lr + 8) * DDc + e0) =
        make_float2(C[nt][2], C[nt][3]);
  }
}

// ---------------------------------------------------------------------------
extern "C" void kernel_launch(void* const* d_in, const int* in_sizes, int n_in,
                              void* d_out, int out_size) {
  const float* Q = (const float*)d_in[0];
  const float* K = (const float*)d_in[1];
  const float* V = (const float*)d_in[2];
  const float* M = (const float*)d_in[3];
  float* X = (float*)d_out;
  (void)in_sizes; (void)n_in; (void)out_size;

  const float scale = powf((float)LLc, -0.25f);

  cudaFuncSetAttribute(ma_pass1, cudaFuncAttributeMaxDynamicSharedMemorySize,
                       65536);
  cudaFuncSetAttribute(ma_pass2, cudaFuncAttributeMaxDynamicSharedMemorySize,
                       32768);

  ma_init<<<(2 * LLc + 255) / 256, 256>>>(M, scale);
  dim3 g1(CHUNKSc, BHc);
  ma_pass1<<<g1, 256, 65536>>>(K, V, M);
  ma_reduce<<<BHc * 64, 128>>>();
  dim3 g2(LLc / 128, BHc * 2);
  ma_pass2<<<g2, 256, 32768>>>(Q, X, scale);
}

// round 6
// speedup vs baseline: 1.5801x; 1.0456x over previous
#include <cuda_runtime.h>
#include <cuda_bf16.h>
#include <stdint.h>
#include <math.h>

// ---------------------------------------------------------------------------
// MomentumAttention (linear attention), bf16 hi/lo split (3-term MMA):
//   Qf = (elu(Q)+1)*scale ; Kf = (elu(K)+1)*mask*scale*mw[l] ; Vf = V*mask
//   KV[d][e] = sum_l Kf[l][d]*Vf[l][e] ;  X = Qf @ KV
// Legacy mma.sync path (tcgen05 unavailable on this build target).
// ---------------------------------------------------------------------------

#define LLc 8192
#define DDc 128
#define BHc 32
#define CHUNKSc 16
#define CLc (LLc / CHUNKSc)   // 512

__device__ float    g_KVp[CHUNKSc * BHc * DDc * DDc];  // per-chunk partials
__device__ float4   g_wm4[2 * LLc / 2];                // {w*m, m, w*m, m} per l-pair
__device__ uint32_t g_KVThi[BHc * DDc * (DDc / 2)];    // [bh][e][d-pair]
__device__ uint32_t g_KVTlo[BHc * DDc * (DDc / 2)];

__device__ __forceinline__ float elup(float x) {
  return x > 0.0f ? x + 1.0f : __expf(x);
}

__device__ __forceinline__ void split_pair(float a, float b,
                                           uint32_t& hi, uint32_t& lo) {
  __nv_bfloat162 h = __floats2bfloat162_rn(a, b);
  hi = *reinterpret_cast<uint32_t*>(&h);
  float ra = a - __bfloat162float(h.x);
  float rb = b - __bfloat162float(h.y);
  __nv_bfloat162 l2 = __floats2bfloat162_rn(ra, rb);
  lo = *reinterpret_cast<uint32_t*>(&l2);
}

__device__ __forceinline__ void mma_bf16(float* c, const uint32_t* a,
                                         const uint32_t* b) {
  asm volatile(
      "mma.sync.aligned.m16n8k16.row.col.f32.bf16.bf16.f32 "
      "{%0,%1,%2,%3},{%4,%5,%6,%7},{%8,%9},{%0,%1,%2,%3};\n"
      : "+f"(c[0]), "+f"(c[1]), "+f"(c[2]), "+f"(c[3])
      : "r"(a[0]), "r"(a[1]), "r"(a[2]), "r"(a[3]), "r"(b[0]), "r"(b[1]));
}

__device__ __forceinline__ void ldsm_x4(uint32_t* r, uint32_t addr) {
  asm volatile(
      "ldmatrix.sync.aligned.m8n8.x4.shared.b16 {%0,%1,%2,%3}, [%4];"
      : "=r"(r[0]), "=r"(r[1]), "=r"(r[2]), "=r"(r[3])
      : "r"(addr));
}

// ---------------------------------------------------------------------------
__global__ void ma_init(const float* __restrict__ mask, float scale) {
  int idx = blockIdx.x * blockDim.x + threadIdx.x;   // 0 .. 8191
  if (idx < 2 * (LLc / 2)) {
    int b = idx >> 12;
    int l = (idx & 4095) * 2;
    float m0 = mask[b * LLc + l];
    float m1 = mask[b * LLc + l + 1];
    float p0 = powf(0.9f, (float)(LLc - l));
    float p1 = powf(0.9f, (float)(LLc - l - 1));
    float w0 = scale * (1.0f - p0) * 10.0f;
    float w1 = scale * (1.0f - p1) * 10.0f;
    g_wm4[idx] = make_float4(w0 * m0, m0, w1 * m1, m1);
  }
}

// ---------------------------------------------------------------------------
// Pass 1: per (chunk, bh): C[d][e] += sum_l Kf[l][d]*Vf[l][e]
// Double-buffered staging: 2 buffers of 32 l (K/V hi/lo, 128 rows x 16 words,
// swizzle chunk^( (row>>1)&3 )), ONE sync per step -> LDG overlaps MMA.
// 8 warps, warp tile 32(d) x 64(e).
// ---------------------------------------------------------------------------
__global__ void __launch_bounds__(256, 2)
ma_pass1(const float* __restrict__ Kin, const float* __restrict__ Vin) {
  extern __shared__ uint32_t sm[];
  // per buffer (8192 words): KHI +0, KLO +2048, VHI +4096, VLO +6144
  const int tid = threadIdx.x;
  const int bh = blockIdx.y;
  const int b = bh >> 4;
  const int chunk = blockIdx.x;
  const float* Kg = Kin + (size_t)bh * LLc * DDc;
  const float* Vg = Vin + (size_t)bh * LLc * DDc;
  const float4* Wg = g_wm4 + (size_t)b * (LLc / 2);

  const int warp = tid >> 5, lane = tid & 31;
  const int g = lane >> 2, t = lane & 3;
  const int q = lane >> 3, r8 = lane & 7;
  const int qh = q >> 1, ql = q & 1;
  const int mo = (warp & 3) * 32;    // d
  const int no = (warp >> 2) * 64;   // e

  uint32_t smb = (uint32_t)__cvta_generic_to_shared(sm);

  // fragment row addresses (word offsets within a buffer)
  int rowA[2], s3A[2];
#pragma unroll
  for (int mt = 0; mt < 2; ++mt) {
    rowA[mt] = mo + mt * 16 + ql * 8 + r8;
    s3A[mt] = (rowA[mt] >> 1) & 3;
  }
  int rowB[4], s3B[4];
#pragma unroll
  for (int np = 0; np < 4; ++np) {
    rowB[np] = no + np * 16 + qh * 8 + r8;
    s3B[np] = (rowB[np] >> 1) & 3;
  }

  const int dst = tid & 127;          // d (K) or e (V) row
  const int lh = (tid >> 7) * 16;     // l-offset half
  const int s3w = (dst >> 1) & 3;     // staging swizzle

  float C[2][8][4];
#pragma unroll
  for (int i = 0; i < 2; i++)
#pragma unroll
    for (int j = 0; j < 8; j++)
#pragma unroll
      for (int p = 0; p < 4; p++) C[i][j][p] = 0.0f;

  const int l0c = chunk * CLc;

  // ---- staging helper: stage 32 l into buffer bsel ----
  auto stage = [&](int s, int bsel) {
    const int base = bsel * 8192;
    const int l0 = l0c + s * 32;
#pragma unroll
    for (int jg = 0; jg < 2; ++jg) {
      int lofs = lh + jg * 8;
      int l = l0 + lofs;
      int chk = lofs >> 3;   // 0..3
      float4 w4[4];
#pragma unroll
      for (int i = 0; i < 4; ++i) w4[i] = Wg[(l >> 1) + i];
      float kf[8], vf[8];
#pragma unroll
      for (int i = 0; i < 4; ++i) {
        float k0 = Kg[(size_t)(l + 2 * i) * DDc + dst];
        float k1 = Kg[(size_t)(l + 2 * i + 1) * DDc + dst];
        float v0 = Vg[(size_t)(l + 2 * i) * DDc + dst];
        float v1 = Vg[(size_t)(l + 2 * i + 1) * DDc + dst];
        kf[2 * i] = elup(k0) * w4[i].x;
        kf[2 * i + 1] = elup(k1) * w4[i].z;
        vf[2 * i] = v0 * w4[i].y;
        vf[2 * i + 1] = v1 * w4[i].w;
      }
      uint4 khi, klo, vhi, vlo;
      split_pair(kf[0], kf[1], khi.x, klo.x);
      split_pair(kf[2], kf[3], khi.y, klo.y);
      split_pair(kf[4], kf[5], khi.z, klo.z);
      split_pair(kf[6], kf[7], khi.w, klo.w);
      split_pair(vf[0], vf[1], vhi.x, vlo.x);
      split_pair(vf[2], vf[3], vhi.y, vlo.y);
      split_pair(vf[4], vf[5], vhi.z, vlo.z);
      split_pair(vf[6], vf[7], vhi.w, vlo.w);
      int off = base + dst * 16 + ((chk ^ s3w) << 2);
      *reinterpret_cast<uint4*>(sm + off) = khi;
      *reinterpret_cast<uint4*>(sm + off + 2048) = klo;
      *reinterpret_cast<uint4*>(sm + off + 4096) = vhi;
      *reinterpret_cast<uint4*>(sm + off + 6144) = vlo;
    }
  };

  // ---- MMA helper over buffer bsel (2 k16 substeps) ----
  auto mmastep = [&](int bsel) {
    const uint32_t base = smb + (uint32_t)bsel * 32768u;
#pragma unroll
    for (int kk = 0; kk < 2; ++kk) {
      uint32_t Ahi[2][4], Alo[2][4];
#pragma unroll
      for (int mt = 0; mt < 2; ++mt) {
        uint32_t a = base + (uint32_t)(rowA[mt] * 64) +
                     (uint32_t)(((kk * 2 + qh) ^ s3A[mt]) << 4);
        ldsm_x4(Ahi[mt], a);
        ldsm_x4(Alo[mt], a + 8192);
      }
#pragma unroll
      for (int np = 0; np < 4; ++np) {
        uint32_t bb = base + 16384u + (uint32_t)(rowB[np] * 64) +
                      (uint32_t)(((kk * 2 + ql) ^ s3B[np]) << 4);
        uint32_t Bh[4], Bl[4];
        ldsm_x4(Bh, bb);
        ldsm_x4(Bl, bb + 8192);
#pragma unroll
        for (int mt = 0; mt < 2; ++mt) {
          mma_bf16(C[mt][2 * np], Ahi[mt], Bh);
          mma_bf16(C[mt][2 * np], Ahi[mt], Bl);
          mma_bf16(C[mt][2 * np], Alo[mt], Bh);
          mma_bf16(C[mt][2 * np + 1], Ahi[mt], Bh + 2);
          mma_bf16(C[mt][2 * np + 1], Ahi[mt], Bl + 2);
          mma_bf16(C[mt][2 * np + 1], Alo[mt], Bh + 2);
        }
      }
    }
  };

  stage(0, 0);
  __syncthreads();
#pragma unroll 1
  for (int s = 0; s < 16; ++s) {
    int bsel = s & 1;
    if (s < 15) stage(s + 1, bsel ^ 1);
    mmastep(bsel);
    __syncthreads();
  }

  float* out = g_KVp + (size_t)(chunk * BHc + bh) * DDc * DDc;
#pragma unroll
  for (int mt = 0; mt < 2; ++mt)
#pragma unroll
    for (int nt = 0; nt < 8; ++nt) {
      int d0 = mo + mt * 16 + g;
      int e0 = no + nt * 8 + t * 2;
      *reinterpret_cast<float2*>(out + (size_t)d0 * DDc + e0) =
          make_float2(C[mt][nt][0], C[mt][nt][1]);
      *reinterpret_cast<float2*>(out + (size_t)(d0 + 8) * DDc + e0) =
          make_float2(C[mt][nt][2], C[mt][nt][3]);
    }
}

// ---------------------------------------------------------------------------
__global__ void __launch_bounds__(128) ma_reduce() {
  const int e = threadIdx.x;
  const int bh = blockIdx.x >> 6;
  const int dp = blockIdx.x & 63;
  const int d = dp * 2;
  float a0 = 0.0f, a1 = 0.0f;
  for (int c = 0; c < CHUNKSc; ++c) {
    const float* p = g_KVp + (size_t)(c * BHc + bh) * DDc * DDc;
    a0 += p[(size_t)d * DDc + e];
    a1 += p[(size_t)(d + 1) * DDc + e];
  }
  uint32_t hi, lo;
  split_pair(a0, a1, hi, lo);
  g_KVThi[(size_t)bh * 8192 + e * 64 + dp] = hi;
  g_KVTlo[(size_t)bh * 8192 + e * 64 + dp] = lo;
}

// ---------------------------------------------------------------------------
// Pass 2 (e-split, mt=2): CTA = (l-chunk of 256) x (bh, e-half of 64).
// B = KV^T e-half smem-resident (32 KB). A (Q) from gmem; warp tile 32l x 64e
// -> B LDSM traffic halved vs 16l.
// ---------------------------------------------------------------------------
__global__ void __launch_bounds__(256, 2)
ma_pass2(const float* __restrict__ Qin, float* __restrict__ Xout, float scale) {
  extern __shared__ uint32_t sm[];
  const int OFF_BHI = 0, OFF_BLO = 4096;

  const int tid = threadIdx.x;
  const int bh = blockIdx.y >> 1;
  const int eh = blockIdx.y & 1;
  const int l0 = blockIdx.x * 256;
  const float* Qg = Qin + (size_t)bh * LLc * DDc;
  float* Xg = Xout + (size_t)bh * LLc * DDc + eh * 64;

  const int warp = tid >> 5, lane = tid & 31;
  const int g = lane >> 2, t = lane & 3;
  const int q = lane >> 3, r8 = lane & 7;
  const int qh = q >> 1, ql = q & 1;
  const int lw = warp * 32;                 // warp's l offset

  uint32_t smb = (uint32_t)__cvta_generic_to_shared(sm);

  // ---- stage B e-half once (swizzled): 64 rows x 16 uint4 ----
  {
    const uint4* shi = reinterpret_cast<const uint4*>(
        g_KVThi + (size_t)bh * 8192 + (size_t)eh * 4096);
    const uint4* slo = reinterpret_cast<const uint4*>(
        g_KVTlo + (size_t)bh * 8192 + (size_t)eh * 4096);
#pragma unroll
    for (int i = 0; i < 4; ++i) {
      int idx4 = tid + i * 256;        // 0..1023
      int e = idx4 >> 4, c = idx4 & 15;
      int w = e * 64 + ((c ^ (e & 7)) << 2);
      *reinterpret_cast<uint4*>(sm + OFF_BHI + w) = shi[idx4];
      *reinterpret_cast<uint4*>(sm + OFF_BLO + w) = slo[idx4];
    }
  }

  uint32_t bBhi[4], bBlo[4];
#pragma unroll
  for (int np = 0; np < 4; ++np) {
    int row = np * 16 + qh * 8 + r8;
    bBhi[np] = smb + (OFF_BHI + row * 64) * 4;
    bBlo[np] = smb + (OFF_BLO + row * 64) * 4;
  }

  const float2* Qp[2];
  const float2* Qp8[2];
#pragma unroll
  for (int mt = 0; mt < 2; ++mt) {
    int row = l0 + lw + mt * 16 + g;
    Qp[mt] = reinterpret_cast<const float2*>(Qg + (size_t)row * DDc);
    Qp8[mt] = Qp[mt] + 8 * (DDc / 2);
  }

  float C[2][8][4];
#pragma unroll
  for (int i = 0; i < 2; i++)
#pragma unroll
    for (int j = 0; j < 8; j++)
#pragma unroll
      for (int p = 0; p < 4; p++) C[i][j][p] = 0.0f;

  __syncthreads();

#pragma unroll 2
  for (int kk = 0; kk < 8; ++kk) {
    uint32_t Ahi[2][4], Alo[2][4];
#pragma unroll
    for (int mt = 0; mt < 2; ++mt) {
      float2 q00 = Qp[mt][kk * 8 + t];
      float2 q01 = Qp[mt][kk * 8 + t + 4];
      float2 q10 = Qp8[mt][kk * 8 + t];
      float2 q11 = Qp8[mt][kk * 8 + t + 4];
      split_pair(elup(q00.x) * scale, elup(q00.y) * scale, Ahi[mt][0], Alo[mt][0]);
      split_pair(elup(q10.x) * scale, elup(q10.y) * scale, Ahi[mt][1], Alo[mt][1]);
      split_pair(elup(q01.x) * scale, elup(q01.y) * scale, Ahi[mt][2], Alo[mt][2]);
      split_pair(elup(q11.x) * scale, elup(q11.y) * scale, Ahi[mt][3], Alo[mt][3]);
    }
    int offB = (((kk * 2 + ql) ^ r8) << 4);
#pragma unroll
    for (int np = 0; np < 4; ++np) {
      uint32_t Bh[4], Bl[4];
      ldsm_x4(Bh, bBhi[np] + offB);
      ldsm_x4(Bl, bBlo[np] + offB);
#pragma unroll
      for (int mt = 0; mt < 2; ++mt) {
        mma_bf16(C[mt][2 * np], Ahi[mt], Bh);
        mma_bf16(C[mt][2 * np], Ahi[mt], Bl);
        mma_bf16(C[mt][2 * np], Alo[mt], Bh);
        mma_bf16(C[mt][2 * np + 1], Ahi[mt], Bh + 2);
        mma_bf16(C[mt][2 * np + 1], Ahi[mt], Bl + 2);
        mma_bf16(C[mt][2 * np + 1], Alo[mt], Bh + 2);
      }
    }
  }
  // ---- epilogue ----
#pragma unroll
  for (int mt = 0; mt < 2; ++mt)
#pragma unroll
    for (int nt = 0; nt < 8; ++nt) {
      int lr = l0 + lw + mt * 16 + g;
      int e0 = nt * 8 + t * 2;
      *reinterpret_cast<float2*>(Xg + (size_t)lr * DDc + e0) =
          make_float2(C[mt][nt][0], C[mt][nt][1]);
      *reinterpret_cast<float2*>(Xg + (size_t)(lr + 8) * DDc + e0) =
          make_float2(C[mt][nt][2], C[mt][nt][3]);
    }
}

// ---------------------------------------------------------------------------
extern "C" void kernel_launch(void* const* d_in, const int* in_sizes, int n_in,
                              void* d_out, int out_size) {
  const float* Q = (const float*)d_in[0];
  const float* K = (const float*)d_in[1];
  const float* V = (const float*)d_in[2];
  const float* M = (const float*)d_in[3];
  float* X = (float*)d_out;
  (void)in_sizes; (void)n_in; (void)out_size;

  const float scale = powf((float)LLc, -0.25f);

  cudaFuncSetAttribute(ma_pass1, cudaFuncAttributeMaxDynamicSharedMemorySize,
                       65536);
  cudaFuncSetAttribute(ma_pass2, cudaFuncAttributeMaxDynamicSharedMemorySize,
                       32768);

  ma_init<<<(LLc + 255) / 256, 256>>>(M, scale);
  dim3 g1(CHUNKSc, BHc);
  ma_pass1<<<g1, 256, 65536>>>(K, V);
  ma_reduce<<<BHc * 64, 128>>>();
  dim3 g2(LLc / 256, BHc * 2);
  ma_pass2<<<g2, 256, 32768>>>(Q, X, scale);
}

// round 8
// speedup vs baseline: 1.7972x; 1.1374x over previous
#include <cuda_runtime.h>
#include <cuda_bf16.h>
#include <stdint.h>
#include <math.h>

// ---------------------------------------------------------------------------
// MomentumAttention (linear attention), bf16 hi/lo split (3-term MMA):
//   Qf = (elu(Q)+1)*scale ; Kf = (elu(K)+1)*mask*scale*mw[l] ; Vf = V*mask
//   KV[d][e] = sum_l Kf[l][d]*Vf[l][e] ;  X = Qf @ KV
// Legacy mma.sync path (tcgen05 unavailable on this build target).
// ---------------------------------------------------------------------------

#define LLc 8192
#define DDc 128
#define BHc 32
#define CHUNKSc 16
#define CLc (LLc / CHUNKSc)   // 512

__device__ float    g_KVp[CHUNKSc * BHc * DDc * DDc];  // per-chunk partials
__device__ float4   g_wm4[2 * LLc / 2];                // {w*m, m, w*m, m} per l-pair
__device__ uint32_t g_KVThi[BHc * DDc * (DDc / 2)];    // [bh][e][d-pair]
__device__ uint32_t g_KVTlo[BHc * DDc * (DDc / 2)];

__device__ __forceinline__ float elup(float x) {
  return x > 0.0f ? x + 1.0f : __expf(x);
}

__device__ __forceinline__ void split_pair(float a, float b,
                                           uint32_t& hi, uint32_t& lo) {
  __nv_bfloat162 h = __floats2bfloat162_rn(a, b);
  hi = *reinterpret_cast<uint32_t*>(&h);
  float ra = a - __bfloat162float(h.x);
  float rb = b - __bfloat162float(h.y);
  __nv_bfloat162 l2 = __floats2bfloat162_rn(ra, rb);
  lo = *reinterpret_cast<uint32_t*>(&l2);
}

__device__ __forceinline__ void mma_bf16(float* c, const uint32_t* a,
                                         const uint32_t* b) {
  asm volatile(
      "mma.sync.aligned.m16n8k16.row.col.f32.bf16.bf16.f32 "
      "{%0,%1,%2,%3},{%4,%5,%6,%7},{%8,%9},{%0,%1,%2,%3};\n"
      : "+f"(c[0]), "+f"(c[1]), "+f"(c[2]), "+f"(c[3])
      : "r"(a[0]), "r"(a[1]), "r"(a[2]), "r"(a[3]), "r"(b[0]), "r"(b[1]));
}

__device__ __forceinline__ void ldsm_x4(uint32_t* r, uint32_t addr) {
  asm volatile(
      "ldmatrix.sync.aligned.m8n8.x4.shared.b16 {%0,%1,%2,%3}, [%4];"
      : "=r"(r[0]), "=r"(r[1]), "=r"(r[2]), "=r"(r[3])
      : "r"(addr));
}

// ---------------------------------------------------------------------------
__global__ void ma_init(const float* __restrict__ mask, float scale) {
  int idx = blockIdx.x * blockDim.x + threadIdx.x;   // 0 .. 8191
  if (idx < 2 * (LLc / 2)) {
    int b = idx >> 12;
    int l = (idx & 4095) * 2;
    float m0 = mask[b * LLc + l];
    float m1 = mask[b * LLc + l + 1];
    float p0 = powf(0.9f, (float)(LLc - l));
    float p1 = powf(0.9f, (float)(LLc - l - 1));
    float w0 = scale * (1.0f - p0) * 10.0f;
    float w1 = scale * (1.0f - p1) * 10.0f;
    g_wm4[idx] = make_float4(w0 * m0, m0, w1 * m1, m1);
  }
}

// ---------------------------------------------------------------------------
// Pass 1: per (chunk, bh): C[d][e] += sum_l Kf[l][d]*Vf[l][e]
// Software pipeline per 16-l step: LDG(s+1)->regs | MMA(s) | transform+STS(s+1).
// 2 smem buffers of 16 l (K/V hi/lo, 128 rows x 8 words, swizzle
// chunk ^ ((row>>2)&1)). 8 warps, warp tile 32(d) x 64(e).
// ---------------------------------------------------------------------------
__global__ void __launch_bounds__(256, 2)
ma_pass1(const float* __restrict__ Kin, const float* __restrict__ Vin) {
  extern __shared__ uint32_t sm[];
  // buffer bsel at word bsel*4096: KHI +0, KLO +1024, VHI +2048, VLO +3072
  const int tid = threadIdx.x;
  const int bh = blockIdx.y;
  const int b = bh >> 4;
  const int chunk = blockIdx.x;
  const float* Kg = Kin + (size_t)bh * LLc * DDc;
  const float* Vg = Vin + (size_t)bh * LLc * DDc;
  const float4* Wg = g_wm4 + (size_t)b * (LLc / 2);

  const int warp = tid >> 5, lane = tid & 31;
  const int g = lane >> 2, t = lane & 3;
  const int q = lane >> 3, r8 = lane & 7;
  const int qh = q >> 1, ql = q & 1;
  const int mo = (warp & 3) * 32;    // d
  const int no = (warp >> 2) * 64;   // e

  uint32_t smb = (uint32_t)__cvta_generic_to_shared(sm);

  // fragment addresses (byte offsets within buffer 0)
  uint32_t aAddrHi[2];
#pragma unroll
  for (int mt = 0; mt < 2; ++mt) {
    int row = mo + mt * 16 + ql * 8 + r8;
    aAddrHi[mt] = smb + (uint32_t)(row * 32) +
                  (uint32_t)(((qh ^ ((row >> 2) & 1))) << 4);
  }
  uint32_t bAddrHi[4];
#pragma unroll
  for (int np = 0; np < 4; ++np) {
    int row = no + np * 16 + qh * 8 + r8;
    bAddrHi[np] = smb + 8192u + (uint32_t)(row * 32) +
                  (uint32_t)(((ql ^ ((row >> 2) & 1))) << 4);
  }

  const int dst = tid & 127;          // d (K) or e (V) row
  const int chk = tid >> 7;           // which 8-l chunk (0/1)
  const int schk = chk ^ ((dst >> 2) & 1);

  float C[2][8][4];
#pragma unroll
  for (int i = 0; i < 2; i++)
#pragma unroll
    for (int j = 0; j < 8; j++)
#pragma unroll
      for (int p = 0; p < 4; p++) C[i][j][p] = 0.0f;

  const int l0c = chunk * CLc;

  float kr[8], vr[8];

  auto loadKV = [&](int s) {
    int l = l0c + s * 16 + chk * 8;
#pragma unroll
    for (int i = 0; i < 8; ++i) {
      kr[i] = Kg[(size_t)(l + i) * DDc + dst];
      vr[i] = Vg[(size_t)(l + i) * DDc + dst];
    }
  };

  auto flushKV = [&](int s, int bsel) {
    int l = l0c + s * 16 + chk * 8;
    float4 w4[4];
#pragma unroll
    for (int i = 0; i < 4; ++i) w4[i] = Wg[(l >> 1) + i];
    float kf[8], vf[8];
#pragma unroll
    for (int i = 0; i < 4; ++i) {
      kf[2 * i] = elup(kr[2 * i]) * w4[i].x;
      kf[2 * i + 1] = elup(kr[2 * i + 1]) * w4[i].z;
      vf[2 * i] = vr[2 * i] * w4[i].y;
      vf[2 * i + 1] = vr[2 * i + 1] * w4[i].w;
    }
    uint4 khi, klo, vhi, vlo;
    split_pair(kf[0], kf[1], khi.x, klo.x);
    split_pair(kf[2], kf[3], khi.y, klo.y);
    split_pair(kf[4], kf[5], khi.z, klo.z);
    split_pair(kf[6], kf[7], khi.w, klo.w);
    split_pair(vf[0], vf[1], vhi.x, vlo.x);
    split_pair(vf[2], vf[3], vhi.y, vlo.y);
    split_pair(vf[4], vf[5], vhi.z, vlo.z);
    split_pair(vf[6], vf[7], vhi.w, vlo.w);
    int off = bsel * 4096 + dst * 8 + (schk << 2);
    *reinterpret_cast<uint4*>(sm + off) = khi;
    *reinterpret_cast<uint4*>(sm + off + 1024) = klo;
    *reinterpret_cast<uint4*>(sm + off + 2048) = vhi;
    *reinterpret_cast<uint4*>(sm + off + 3072) = vlo;
  };

  auto mmastep = [&](int bsel) {
    const uint32_t bb = (uint32_t)bsel * 16384u;
    uint32_t Ahi[2][4], Alo[2][4];
#pragma unroll
    for (int mt = 0; mt < 2; ++mt) {
      ldsm_x4(Ahi[mt], aAddrHi[mt] + bb);
      ldsm_x4(Alo[mt], aAddrHi[mt] + bb + 4096u);
    }
#pragma unroll
    for (int np = 0; np < 4; ++np) {
      uint32_t Bh[4], Bl[4];
      ldsm_x4(Bh, bAddrHi[np] + bb);
      ldsm_x4(Bl, bAddrHi[np] + bb + 4096u);
#pragma unroll
      for (int mt = 0; mt < 2; ++mt) {
        mma_bf16(C[mt][2 * np], Ahi[mt], Bh);
        mma_bf16(C[mt][2 * np], Ahi[mt], Bl);
        mma_bf16(C[mt][2 * np], Alo[mt], Bh);
        mma_bf16(C[mt][2 * np + 1], Ahi[mt], Bh + 2);
        mma_bf16(C[mt][2 * np + 1], Ahi[mt], Bl + 2);
        mma_bf16(C[mt][2 * np + 1], Alo[mt], Bh + 2);
      }
    }
  };

  // prologue
  loadKV(0);
  flushKV(0, 0);
  __syncthreads();

#pragma unroll 1
  for (int s = 0; s < 32; ++s) {
    int bsel = s & 1;
    if (s < 31) loadKV(s + 1);       // LDGs in flight during MMAs
    mmastep(bsel);
    if (s < 31) flushKV(s + 1, bsel ^ 1);
    __syncthreads();
  }

  float* out = g_KVp + (size_t)(chunk * BHc + bh) * DDc * DDc;
#pragma unroll
  for (int mt = 0; mt < 2; ++mt)
#pragma unroll
    for (int nt = 0; nt < 8; ++nt) {
      int d0 = mo + mt * 16 + g;
      int e0 = no + nt * 8 + t * 2;
      *reinterpret_cast<float2*>(out + (size_t)d0 * DDc + e0) =
          make_float2(C[mt][nt][0], C[mt][nt][1]);
      *reinterpret_cast<float2*>(out + (size_t)(d0 + 8) * DDc + e0) =
          make_float2(C[mt][nt][2], C[mt][nt][3]);
    }
}

// ---------------------------------------------------------------------------
__global__ void __launch_bounds__(128) ma_reduce() {
  const int e = threadIdx.x;
  const int bh = blockIdx.x >> 6;
  const int dp = blockIdx.x & 63;
  const int d = dp * 2;
  float a0 = 0.0f, a1 = 0.0f;
  for (int c = 0; c < CHUNKSc; ++c) {
    const float* p = g_KVp + (size_t)(c * BHc + bh) * DDc * DDc;
    a0 += p[(size_t)d * DDc + e];
    a1 += p[(size_t)(d + 1) * DDc + e];
  }
  uint32_t hi, lo;
  split_pair(a0, a1, hi, lo);
  g_KVThi[(size_t)bh * 8192 + e * 64 + dp] = hi;
  g_KVTlo[(size_t)bh * 8192 + e * 64 + dp] = lo;
}

// ---------------------------------------------------------------------------
// Pass 2 (e-split): CTA = (128 l) x (bh, e-half of 64).
// B = KV^T e-half smem-resident (32 KB). Q staged via cp.async 3-buffer ring
// (prefetch 1 kk ahead), rows of 16 words with chunk^(row&3) XOR swizzle
// (16B-aligned cp.async dst, conflict-free stage & read).
// Warp tile 16l x 64e; 3 CTAs/SM.
// smem words: BHI[0,4096) BLO[4096,8192) Q[8192, 8192+3*2048)
// ---------------------------------------------------------------------------
#define QOFF 8192
#define QBUF 2048

__global__ void __launch_bounds__(256, 3)
ma_pass2(const float* __restrict__ Qin, float* __restrict__ Xout, float scale) {
  extern __shared__ uint32_t sm[];

  const int tid = threadIdx.x;
  const int bh = blockIdx.y >> 1;
  const int eh = blockIdx.y & 1;
  const int l0 = blockIdx.x * 128;
  const float* Qg = Qin + (size_t)bh * LLc * DDc;
  float* Xg = Xout + (size_t)bh * LLc * DDc + eh * 64;

  const int warp = tid >> 5, lane = tid & 31;
  const int g = lane >> 2, t = lane & 3;
  const int q = lane >> 3, r8 = lane & 7;
  const int qh = q >> 1, ql = q & 1;
  const int lw = warp * 16;                 // warp's l offset

  uint32_t smb = (uint32_t)__cvta_generic_to_shared(sm);

  // ---- stage B e-half once (swizzled): 64 rows x 16 uint4 ----
  {
    const uint4* shi = reinterpret_cast<const uint4*>(
        g_KVThi + (size_t)bh * 8192 + (size_t)eh * 4096);
    const uint4* slo = reinterpret_cast<const uint4*>(
        g_KVTlo + (size_t)bh * 8192 + (size_t)eh * 4096);
#pragma unroll
    for (int i = 0; i < 4; ++i) {
      int idx4 = tid + i * 256;        // 0..1023
      int e = idx4 >> 4, c = idx4 & 15;
      int w = e * 64 + ((c ^ (e & 7)) << 2);
      *reinterpret_cast<uint4*>(sm + w) = shi[idx4];
      *reinterpret_cast<uint4*>(sm + 4096 + w) = slo[idx4];
    }
  }

  uint32_t bBhi[4], bBlo[4];
#pragma unroll
  for (int np = 0; np < 4; ++np) {
    int row = np * 16 + qh * 8 + r8;
    bBhi[np] = smb + (uint32_t)(row * 64) * 4u;
    bBlo[np] = smb + (4096u + (uint32_t)(row * 64)) * 4u;
  }

  // ---- Q cp.async ring: rows of 16 words, chunk ^ (row&3) swizzle ----
  const int crow = tid >> 2, ccol = tid & 3;
  auto cpQ = [&](int kk) {
    uint32_t sb = smb + (uint32_t)(QOFF + (kk % 3) * QBUF) * 4u;
    const float* gb = Qg + (size_t)l0 * DDc + kk * 16;
#pragma unroll
    for (int i = 0; i < 2; ++i) {
      int row = crow + i * 64;
      int pc = ccol ^ (row & 3);
      uint32_t s = sb + (uint32_t)(row * 16 + pc * 4) * 4u;
      const float* gp = gb + (size_t)row * DDc + ccol * 4;
      asm volatile("cp.async.cg.shared.global [%0], [%1], 16;\n"
                   :: "r"(s), "l"(gp));
    }
    asm volatile("cp.async.commit_group;\n" ::: "memory");
  };

  // logical word w of row -> physical word offset within Q buffer
  auto qword = [](int row, int w) {
    return row * 16 + ((((w >> 2) ^ (row & 3))) << 2) + (w & 3);
  };

  float C[8][4];
#pragma unroll
  for (int j = 0; j < 8; j++)
#pragma unroll
    for (int p = 0; p < 4; p++) C[j][p] = 0.0f;

  cpQ(0);
  __syncthreads();   // B stage visible before main loop

#pragma unroll 1
  for (int kk = 0; kk < 8; ++kk) {
    if (kk < 7) {
      cpQ(kk + 1);
      asm volatile("cp.async.wait_group 1;\n" ::: "memory");
    } else {
      asm volatile("cp.async.wait_group 0;\n" ::: "memory");
    }
    __syncthreads();

    const uint32_t* qb = sm + QOFF + (kk % 3) * QBUF;
    int r0 = lw + g, r1 = lw + g + 8;
    float2 q00 = *reinterpret_cast<const float2*>(qb + qword(r0, t * 2));
    float2 q01 = *reinterpret_cast<const float2*>(qb + qword(r0, t * 2 + 8));
    float2 q10 = *reinterpret_cast<const float2*>(qb + qword(r1, t * 2));
    float2 q11 = *reinterpret_cast<const float2*>(qb + qword(r1, t * 2 + 8));

    uint32_t Ahi[4], Alo[4];
    split_pair(elup(q00.x) * scale, elup(q00.y) * scale, Ahi[0], Alo[0]);
    split_pair(elup(q10.x) * scale, elup(q10.y) * scale, Ahi[1], Alo[1]);
    split_pair(elup(q01.x) * scale, elup(q01.y) * scale, Ahi[2], Alo[2]);
    split_pair(elup(q11.x) * scale, elup(q11.y) * scale, Ahi[3], Alo[3]);

    int offB = (((kk * 2 + ql) ^ r8) << 4);
#pragma unroll
    for (int np = 0; np < 4; ++np) {
      uint32_t Bh[4], Bl[4];
      ldsm_x4(Bh, bBhi[np] + offB);
      ldsm_x4(Bl, bBlo[np] + offB);
      mma_bf16(C[2 * np], Ahi, Bh);
      mma_bf16(C[2 * np], Ahi, Bl);
      mma_bf16(C[2 * np], Alo, Bh);
      mma_bf16(C[2 * np + 1], Ahi, Bh + 2);
      mma_bf16(C[2 * np + 1], Ahi, Bl + 2);
      mma_bf16(C[2 * np + 1], Alo, Bh + 2);
    }
  }

  // ---- epilogue ----
#pragma unroll
  for (int nt = 0; nt < 8; ++nt) {
    int lr = l0 + lw + g;
    int e0 = nt * 8 + t * 2;
    *reinterpret_cast<float2*>(Xg + (size_t)lr * DDc + e0) =
        make_float2(C[nt][0], C[nt][1]);
    *reinterpret_cast<float2*>(Xg + (size_t)(lr + 8) * DDc + e0) =
        make_float2(C[nt][2], C[nt][3]);
  }
}

// ---------------------------------------------------------------------------
extern "C" void kernel_launch(void* const* d_in, const int* in_sizes, int n_in,
                              void* d_out, int out_size) {
  const float* Q = (const float*)d_in[0];
  const float* K = (const float*)d_in[1];
  const float* V = (const float*)d_in[2];
  const float* M = (const float*)d_in[3];
  float* X = (float*)d_out;
  (void)in_sizes; (void)n_in; (void)out_size;

  const float scale = powf((float)LLc, -0.25f);

  cudaFuncSetAttribute(ma_pass1, cudaFuncAttributeMaxDynamicSharedMemorySize,
                       32768);
  cudaFuncSetAttribute(ma_pass2, cudaFuncAttributeMaxDynamicSharedMemorySize,
                       (QOFF + 3 * QBUF) * 4);

  ma_init<<<(LLc + 255) / 256, 256>>>(M, scale);
  dim3 g1(CHUNKSc, BHc);
  ma_pass1<<<g1, 256, 32768>>>(K, V);
  ma_reduce<<<BHc * 64, 128>>>();
  dim3 g2(LLc / 128, BHc * 2);
  ma_pass2<<<g2, 256, (QOFF + 3 * QBUF) * 4>>>(Q, X, scale);
}

// round 9
// speedup vs baseline: 1.8781x; 1.0450x over previous
#include <cuda_runtime.h>
#include <cuda_bf16.h>
#include <stdint.h>
#include <math.h>

// ---------------------------------------------------------------------------
// MomentumAttention (linear attention), bf16 hi/lo split (3-term MMA):
//   Qf = (elu(Q)+1)*scale ; Kf = (elu(K)+1)*mask*scale*mw[l] ; Vf = V*mask
//   KV[d][e] = sum_l Kf[l][d]*Vf[l][e] ;  X = Qf @ KV
// Legacy mma.sync path (tcgen05 unavailable on this build target).
// ---------------------------------------------------------------------------

#define LLc 8192
#define DDc 128
#define BHc 32
#define CHUNKSc 16
#define CLc (LLc / CHUNKSc)   // 512

__device__ float    g_KVp[CHUNKSc * BHc * DDc * DDc];  // per-chunk partials
__device__ float4   g_wm4[2 * LLc / 2];                // {w*m, m, w*m, m} per l-pair
__device__ uint32_t g_KVThi[BHc * DDc * (DDc / 2)];    // [bh][e][d-pair]
__device__ uint32_t g_KVTlo[BHc * DDc * (DDc / 2)];

__device__ __forceinline__ float elup(float x) {
  return x > 0.0f ? x + 1.0f : __expf(x);
}

__device__ __forceinline__ void split_pair(float a, float b,
                                           uint32_t& hi, uint32_t& lo) {
  __nv_bfloat162 h = __floats2bfloat162_rn(a, b);
  hi = *reinterpret_cast<uint32_t*>(&h);
  float ra = a - __bfloat162float(h.x);
  float rb = b - __bfloat162float(h.y);
  __nv_bfloat162 l2 = __floats2bfloat162_rn(ra, rb);
  lo = *reinterpret_cast<uint32_t*>(&l2);
}

__device__ __forceinline__ void mma_bf16(float* c, const uint32_t* a,
                                         const uint32_t* b) {
  asm volatile(
      "mma.sync.aligned.m16n8k16.row.col.f32.bf16.bf16.f32 "
      "{%0,%1,%2,%3},{%4,%5,%6,%7},{%8,%9},{%0,%1,%2,%3};\n"
      : "+f"(c[0]), "+f"(c[1]), "+f"(c[2]), "+f"(c[3])
      : "r"(a[0]), "r"(a[1]), "r"(a[2]), "r"(a[3]), "r"(b[0]), "r"(b[1]));
}

__device__ __forceinline__ void ldsm_x4(uint32_t* r, uint32_t addr) {
  asm volatile(
      "ldmatrix.sync.aligned.m8n8.x4.shared.b16 {%0,%1,%2,%3}, [%4];"
      : "=r"(r[0]), "=r"(r[1]), "=r"(r[2]), "=r"(r[3])
      : "r"(addr));
}

// ---------------------------------------------------------------------------
__global__ void ma_init(const float* __restrict__ mask, float scale) {
  int idx = blockIdx.x * blockDim.x + threadIdx.x;   // 0 .. 8191
  if (idx < 2 * (LLc / 2)) {
    int b = idx >> 12;
    int l = (idx & 4095) * 2;
    float m0 = mask[b * LLc + l];
    float m1 = mask[b * LLc + l + 1];
    float p0 = powf(0.9f, (float)(LLc - l));
    float p1 = powf(0.9f, (float)(LLc - l - 1));
    float w0 = scale * (1.0f - p0) * 10.0f;
    float w1 = scale * (1.0f - p1) * 10.0f;
    g_wm4[idx] = make_float4(w0 * m0, m0, w1 * m1, m1);
  }
}

// ---------------------------------------------------------------------------
// Pass 1: per (chunk, bh): C[d][e] += sum_l Kf[l][d]*Vf[l][e]
// cp.async raw K/V ring (3 buffers of 16 l, fp32) feeds a transform stage
// (smem->bf16 hi/lo double buffer), MMAs overlap both. One sync per step.
// smem (words): bf16 buffers [0,8192): buffer b at b*4096
//                 {KHI +0, KLO +1024, VHI +2048, VLO +3072}
//               raw ring [8192, 8192+3*4096): {rawK +0, rawV +2048}
// 8 warps, warp tile 32(d) x 64(e).
// ---------------------------------------------------------------------------
__global__ void __launch_bounds__(256, 2)
ma_pass1(const float* __restrict__ Kin, const float* __restrict__ Vin) {
  extern __shared__ uint32_t sm[];
  const int tid = threadIdx.x;
  const int bh = blockIdx.y;
  const int b = bh >> 4;
  const int chunk = blockIdx.x;
  const float* Kg = Kin + (size_t)bh * LLc * DDc;
  const float* Vg = Vin + (size_t)bh * LLc * DDc;
  const float4* Wg = g_wm4 + (size_t)b * (LLc / 2);

  const int warp = tid >> 5, lane = tid & 31;
  const int g = lane >> 2, t = lane & 3;
  const int q = lane >> 3, r8 = lane & 7;
  const int qh = q >> 1, ql = q & 1;
  const int mo = (warp & 3) * 32;    // d
  const int no = (warp >> 2) * 64;   // e

  uint32_t smb = (uint32_t)__cvta_generic_to_shared(sm);

  // fragment addresses (byte offsets within bf16 buffer 0)
  uint32_t aAddrHi[2];
#pragma unroll
  for (int mt = 0; mt < 2; ++mt) {
    int row = mo + mt * 16 + ql * 8 + r8;
    aAddrHi[mt] = smb + (uint32_t)(row * 32) +
                  (uint32_t)(((qh ^ ((row >> 2) & 1))) << 4);
  }
  uint32_t bAddrHi[4];
#pragma unroll
  for (int np = 0; np < 4; ++np) {
    int row = no + np * 16 + qh * 8 + r8;
    bAddrHi[np] = smb + 8192u + (uint32_t)(row * 32) +
                  (uint32_t)(((ql ^ ((row >> 2) & 1))) << 4);
  }

  const int dst = tid & 127;          // d (K) or e (V) row
  const int chk = tid >> 7;           // which 8-l chunk (0/1)
  const int schk = chk ^ ((dst >> 2) & 1);

  float C[2][8][4];
#pragma unroll
  for (int i = 0; i < 2; i++)
#pragma unroll
    for (int j = 0; j < 8; j++)
#pragma unroll
      for (int p = 0; p < 4; p++) C[i][j][p] = 0.0f;

  const int l0c = chunk * CLc;

  // ---- cp.async of raw K/V step s into ring buffer s%3 ----
  const int crow = tid >> 4;          // 0..15 (l within step)
  const int ccol = tid & 15;          // 0..15 (4-word chunk)
  auto cpKV = [&](int s) {
    uint32_t kb = smb + (uint32_t)(8192 + (s % 3) * 4096) * 4u;
    uint32_t vb = kb + 8192u;
    const float* kg = Kg + (size_t)(l0c + s * 16 + crow) * DDc + ccol * 4;
    const float* vg = Vg + (size_t)(l0c + s * 16 + crow) * DDc + ccol * 4;
    uint32_t so = (uint32_t)(crow * 128 + ccol * 4) * 4u;
    asm volatile("cp.async.cg.shared.global [%0], [%1], 16;\n"
                 :: "r"(kb + so), "l"(kg));
    asm volatile("cp.async.cg.shared.global [%0], [%1], 16;\n"
                 :: "r"(kb + so + 256u), "l"(kg + 64));
    asm volatile("cp.async.cg.shared.global [%0], [%1], 16;\n"
                 :: "r"(vb + so), "l"(vg));
    asm volatile("cp.async.cg.shared.global [%0], [%1], 16;\n"
                 :: "r"(vb + so + 256u), "l"(vg + 64));
    asm volatile("cp.async.commit_group;\n" ::: "memory");
  };

  // ---- transform raw(s) -> bf16 buffer (s&1) ----
  auto transform = [&](int s) {
    const uint32_t* kb = sm + 8192 + (s % 3) * 4096;
    const uint32_t* vb = kb + 2048;
    int l = l0c + s * 16 + chk * 8;
    float4 w4[4];
#pragma unroll
    for (int i = 0; i < 4; ++i) w4[i] = Wg[(l >> 1) + i];
    float kf[8], vf[8];
#pragma unroll
    for (int i = 0; i < 4; ++i) {
      int rw = (chk * 8 + 2 * i) * 128 + dst;
      float k0 = __uint_as_float(kb[rw]);
      float k1 = __uint_as_float(kb[rw + 128]);
      float v0 = __uint_as_float(vb[rw]);
      float v1 = __uint_as_float(vb[rw + 128]);
      kf[2 * i] = elup(k0) * w4[i].x;
      kf[2 * i + 1] = elup(k1) * w4[i].z;
      vf[2 * i] = v0 * w4[i].y;
      vf[2 * i + 1] = v1 * w4[i].w;
    }
    uint4 khi, klo, vhi, vlo;
    split_pair(kf[0], kf[1], khi.x, klo.x);
    split_pair(kf[2], kf[3], khi.y, klo.y);
    split_pair(kf[4], kf[5], khi.z, klo.z);
    split_pair(kf[6], kf[7], khi.w, klo.w);
    split_pair(vf[0], vf[1], vhi.x, vlo.x);
    split_pair(vf[2], vf[3], vhi.y, vlo.y);
    split_pair(vf[4], vf[5], vhi.z, vlo.z);
    split_pair(vf[6], vf[7], vhi.w, vlo.w);
    int off = (s & 1) * 4096 + dst * 8 + (schk << 2);
    *reinterpret_cast<uint4*>(sm + off) = khi;
    *reinterpret_cast<uint4*>(sm + off + 1024) = klo;
    *reinterpret_cast<uint4*>(sm + off + 2048) = vhi;
    *reinterpret_cast<uint4*>(sm + off + 3072) = vlo;
  };

  auto mmastep = [&](int bsel) {
    const uint32_t bb = (uint32_t)bsel * 16384u;
    uint32_t Ahi[2][4], Alo[2][4];
#pragma unroll
    for (int mt = 0; mt < 2; ++mt) {
      ldsm_x4(Ahi[mt], aAddrHi[mt] + bb);
      ldsm_x4(Alo[mt], aAddrHi[mt] + bb + 4096u);
    }
#pragma unroll
    for (int np = 0; np < 4; ++np) {
      uint32_t Bh[4], Bl[4];
      ldsm_x4(Bh, bAddrHi[np] + bb);
      ldsm_x4(Bl, bAddrHi[np] + bb + 4096u);
#pragma unroll
      for (int mt = 0; mt < 2; ++mt) {
        mma_bf16(C[mt][2 * np], Ahi[mt], Bh);
        mma_bf16(C[mt][2 * np], Ahi[mt], Bl);
        mma_bf16(C[mt][2 * np], Alo[mt], Bh);
        mma_bf16(C[mt][2 * np + 1], Ahi[mt], Bh + 2);
        mma_bf16(C[mt][2 * np + 1], Ahi[mt], Bl + 2);
        mma_bf16(C[mt][2 * np + 1], Alo[mt], Bh + 2);
      }
    }
  };

  // ---- prologue: 3 groups in flight; transform step 0 ----
  cpKV(0);
  cpKV(1);
  cpKV(2);
  asm volatile("cp.async.wait_group 2;\n" ::: "memory");   // group 0 done
  __syncthreads();                                          // publish raw 0
  transform(0);
  asm volatile("cp.async.wait_group 1;\n" ::: "memory");   // group 1 done
  __syncthreads();                                          // publish raw 1 + bf16 buf 0

#pragma unroll 1
  for (int s = 0; s < 32; ++s) {
    if (s < 29) cpKV(s + 3);
    mmastep(s & 1);
    if (s < 31) transform(s + 1);   // raw (s+1) published by previous sync
    if (s < 29) {
      asm volatile("cp.async.wait_group 1;\n" ::: "memory");  // group s+2 done
    } else if (s == 29) {
      asm volatile("cp.async.wait_group 0;\n" ::: "memory");  // group 31 done
    }
    __syncthreads();
  }

  float* out = g_KVp + (size_t)(chunk * BHc + bh) * DDc * DDc;
#pragma unroll
  for (int mt = 0; mt < 2; ++mt)
#pragma unroll
    for (int nt = 0; nt < 8; ++nt) {
      int d0 = mo + mt * 16 + g;
      int e0 = no + nt * 8 + t * 2;
      *reinterpret_cast<float2*>(out + (size_t)d0 * DDc + e0) =
          make_float2(C[mt][nt][0], C[mt][nt][1]);
      *reinterpret_cast<float2*>(out + (size_t)(d0 + 8) * DDc + e0) =
          make_float2(C[mt][nt][2], C[mt][nt][3]);
    }
}

// ---------------------------------------------------------------------------
__global__ void __launch_bounds__(128) ma_reduce() {
  const int e = threadIdx.x;
  const int bh = blockIdx.x >> 6;
  const int dp = blockIdx.x & 63;
  const int d = dp * 2;
  float a0 = 0.0f, a1 = 0.0f;
  for (int c = 0; c < CHUNKSc; ++c) {
    const float* p = g_KVp + (size_t)(c * BHc + bh) * DDc * DDc;
    a0 += p[(size_t)d * DDc + e];
    a1 += p[(size_t)(d + 1) * DDc + e];
  }
  uint32_t hi, lo;
  split_pair(a0, a1, hi, lo);
  g_KVThi[(size_t)bh * 8192 + e * 64 + dp] = hi;
  g_KVTlo[(size_t)bh * 8192 + e * 64 + dp] = lo;
}

// ---------------------------------------------------------------------------
// Pass 2 (e-split): unchanged from R8.
// ---------------------------------------------------------------------------
#define QOFF 8192
#define QBUF 2048

__global__ void __launch_bounds__(256, 3)
ma_pass2(const float* __restrict__ Qin, float* __restrict__ Xout, float scale) {
  extern __shared__ uint32_t sm[];

  const int tid = threadIdx.x;
  const int bh = blockIdx.y >> 1;
  const int eh = blockIdx.y & 1;
  const int l0 = blockIdx.x * 128;
  const float* Qg = Qin + (size_t)bh * LLc * DDc;
  float* Xg = Xout + (size_t)bh * LLc * DDc + eh * 64;

  const int warp = tid >> 5, lane = tid & 31;
  const int g = lane >> 2, t = lane & 3;
  const int q = lane >> 3, r8 = lane & 7;
  const int qh = q >> 1, ql = q & 1;
  const int lw = warp * 16;                 // warp's l offset

  uint32_t smb = (uint32_t)__cvta_generic_to_shared(sm);

  // ---- stage B e-half once (swizzled): 64 rows x 16 uint4 ----
  {
    const uint4* shi = reinterpret_cast<const uint4*>(
        g_KVThi + (size_t)bh * 8192 + (size_t)eh * 4096);
    const uint4* slo = reinterpret_cast<const uint4*>(
        g_KVTlo + (size_t)bh * 8192 + (size_t)eh * 4096);
#pragma unroll
    for (int i = 0; i < 4; ++i) {
      int idx4 = tid + i * 256;        // 0..1023
      int e = idx4 >> 4, c = idx4 & 15;
      int w = e * 64 + ((c ^ (e & 7)) << 2);
      *reinterpret_cast<uint4*>(sm + w) = shi[idx4];
      *reinterpret_cast<uint4*>(sm + 4096 + w) = slo[idx4];
    }
  }

  uint32_t bBhi[4], bBlo[4];
#pragma unroll
  for (int np = 0; np < 4; ++np) {
    int row = np * 16 + qh * 8 + r8;
    bBhi[np] = smb + (uint32_t)(row * 64) * 4u;
    bBlo[np] = smb + (4096u + (uint32_t)(row * 64)) * 4u;
  }

  // ---- Q cp.async ring: rows of 16 words, chunk ^ (row&3) swizzle ----
  const int crow = tid >> 2, ccol = tid & 3;
  auto cpQ = [&](int kk) {
    uint32_t sb = smb + (uint32_t)(QOFF + (kk % 3) * QBUF) * 4u;
    const float* gb = Qg + (size_t)l0 * DDc + kk * 16;
#pragma unroll
    for (int i = 0; i < 2; ++i) {
      int row = crow + i * 64;
      int pc = ccol ^ (row & 3);
      uint32_t s = sb + (uint32_t)(row * 16 + pc * 4) * 4u;
      const float* gp = gb + (size_t)row * DDc + ccol * 4;
      asm volatile("cp.async.cg.shared.global [%0], [%1], 16;\n"
                   :: "r"(s), "l"(gp));
    }
    asm volatile("cp.async.commit_group;\n" ::: "memory");
  };

  auto qword = [](int row, int w) {
    return row * 16 + ((((w >> 2) ^ (row & 3))) << 2) + (w & 3);
  };

  float C[8][4];
#pragma unroll
  for (int j = 0; j < 8; j++)
#pragma unroll
    for (int p = 0; p < 4; p++) C[j][p] = 0.0f;

  cpQ(0);
  __syncthreads();   // B stage visible before main loop

#pragma unroll 1
  for (int kk = 0; kk < 8; ++kk) {
    if (kk < 7) {
      cpQ(kk + 1);
      asm volatile("cp.async.wait_group 1;\n" ::: "memory");
    } else {
      asm volatile("cp.async.wait_group 0;\n" ::: "memory");
    }
    __syncthreads();

    const uint32_t* qb = sm + QOFF + (kk % 3) * QBUF;
    int r0 = lw + g, r1 = lw + g + 8;
    float2 q00 = *reinterpret_cast<const float2*>(qb + qword(r0, t * 2));
    float2 q01 = *reinterpret_cast<const float2*>(qb + qword(r0, t * 2 + 8));
    float2 q10 = *reinterpret_cast<const float2*>(qb + qword(r1, t * 2));
    float2 q11 = *reinterpret_cast<const float2*>(qb + qword(r1, t * 2 + 8));

    uint32_t Ahi[4], Alo[4];
    split_pair(elup(q00.x) * scale, elup(q00.y) * scale, Ahi[0], Alo[0]);
    split_pair(elup(q10.x) * scale, elup(q10.y) * scale, Ahi[1], Alo[1]);
    split_pair(elup(q01.x) * scale, elup(q01.y) * scale, Ahi[2], Alo[2]);
    split_pair(elup(q11.x) * scale, elup(q11.y) * scale, Ahi[3], Alo[3]);

    int offB = (((kk * 2 + ql) ^ r8) << 4);
#pragma unroll
    for (int np = 0; np < 4; ++np) {
      uint32_t Bh[4], Bl[4];
      ldsm_x4(Bh, bBhi[np] + offB);
      ldsm_x4(Bl, bBlo[np] + offB);
      mma_bf16(C[2 * np], Ahi, Bh);
      mma_bf16(C[2 * np], Ahi, Bl);
      mma_bf16(C[2 * np], Alo, Bh);
      mma_bf16(C[2 * np + 1], Ahi, Bh + 2);
      mma_bf16(C[2 * np + 1], Ahi, Bl + 2);
      mma_bf16(C[2 * np + 1], Alo, Bh + 2);
    }
  }

  // ---- epilogue ----
#pragma unroll
  for (int nt = 0; nt < 8; ++nt) {
    int lr = l0 + lw + g;
    int e0 = nt * 8 + t * 2;
    *reinterpret_cast<float2*>(Xg + (size_t)lr * DDc + e0) =
        make_float2(C[nt][0], C[nt][1]);
    *reinterpret_cast<float2*>(Xg + (size_t)(lr + 8) * DDc + e0) =
        make_float2(C[nt][2], C[nt][3]);
  }
}

// ---------------------------------------------------------------------------
extern "C" void kernel_launch(void* const* d_in, const int* in_sizes, int n_in,
                              void* d_out, int out_size) {
  const float* Q = (const float*)d_in[0];
  const float* K = (const float*)d_in[1];
  const float* V = (const float*)d_in[2];
  const float* M = (const float*)d_in[3];
  float* X = (float*)d_out;
  (void)in_sizes; (void)n_in; (void)out_size;

  const float scale = powf((float)LLc, -0.25f);

  cudaFuncSetAttribute(ma_pass1, cudaFuncAttributeMaxDynamicSharedMemorySize,
                       (8192 + 3 * 4096) * 4);
  cudaFuncSetAttribute(ma_pass2, cudaFuncAttributeMaxDynamicSharedMemorySize,
                       (QOFF + 3 * QBUF) * 4);

  ma_init<<<(LLc + 255) / 256, 256>>>(M, scale);
  dim3 g1(CHUNKSc, BHc);
  ma_pass1<<<g1, 256, (8192 + 3 * 4096) * 4>>>(K, V);
  ma_reduce<<<BHc * 64, 128>>>();
  dim3 g2(LLc / 128, BHc * 2);
  ma_pass2<<<g2, 256, (QOFF + 3 * QBUF) * 4>>>(Q, X, scale);
}

// round 10
// speedup vs baseline: 1.9579x; 1.0425x over previous
#include <cuda_runtime.h>
#include <cuda_bf16.h>
#include <stdint.h>
#include <math.h>

// ---------------------------------------------------------------------------
// MomentumAttention (linear attention), bf16 hi/lo split (3-term MMA):
//   Qf = (elu(Q)+1)*scale ; Kf = (elu(K)+1)*mask*scale*mw[l] ; Vf = V*mask
//   KV[d][e] = sum_l Kf[l][d]*Vf[l][e] ;  X = Qf @ KV
// Legacy mma.sync path (tcgen05 unavailable on this build target).
// ---------------------------------------------------------------------------

#define LLc 8192
#define DDc 128
#define BHc 32
#define CHUNKSc 16
#define CLc (LLc / CHUNKSc)   // 512

__device__ float    g_KVp[CHUNKSc * BHc * DDc * DDc];  // per-chunk partials
__device__ float4   g_wm4[2 * LLc / 2];                // {w*m, m, w*m, m} per l-pair
__device__ uint32_t g_KVThi[BHc * DDc * (DDc / 2)];    // [bh][e][d-pair]
__device__ uint32_t g_KVTlo[BHc * DDc * (DDc / 2)];

__device__ __forceinline__ float elup(float x) {
  return x > 0.0f ? x + 1.0f : __expf(x);
}

__device__ __forceinline__ void split_pair(float a, float b,
                                           uint32_t& hi, uint32_t& lo) {
  __nv_bfloat162 h = __floats2bfloat162_rn(a, b);
  hi = *reinterpret_cast<uint32_t*>(&h);
  float ra = a - __bfloat162float(h.x);
  float rb = b - __bfloat162float(h.y);
  __nv_bfloat162 l2 = __floats2bfloat162_rn(ra, rb);
  lo = *reinterpret_cast<uint32_t*>(&l2);
}

__device__ __forceinline__ void mma_bf16(float* c, const uint32_t* a,
                                         const uint32_t* b) {
  asm volatile(
      "mma.sync.aligned.m16n8k16.row.col.f32.bf16.bf16.f32 "
      "{%0,%1,%2,%3},{%4,%5,%6,%7},{%8,%9},{%0,%1,%2,%3};\n"
      : "+f"(c[0]), "+f"(c[1]), "+f"(c[2]), "+f"(c[3])
      : "r"(a[0]), "r"(a[1]), "r"(a[2]), "r"(a[3]), "r"(b[0]), "r"(b[1]));
}

__device__ __forceinline__ void ldsm_x4(uint32_t* r, uint32_t addr) {
  asm volatile(
      "ldmatrix.sync.aligned.m8n8.x4.shared.b16 {%0,%1,%2,%3}, [%4];"
      : "=r"(r[0]), "=r"(r[1]), "=r"(r[2]), "=r"(r[3])
      : "r"(addr));
}

// ---------------------------------------------------------------------------
__global__ void ma_init(const float* __restrict__ mask, float scale) {
  int idx = blockIdx.x * blockDim.x + threadIdx.x;   // 0 .. 8191
  if (idx < 2 * (LLc / 2)) {
    int b = idx >> 12;
    int l = (idx & 4095) * 2;
    float m0 = mask[b * LLc + l];
    float m1 = mask[b * LLc + l + 1];
    float p0 = powf(0.9f, (float)(LLc - l));
    float p1 = powf(0.9f, (float)(LLc - l - 1));
    float w0 = scale * (1.0f - p0) * 10.0f;
    float w1 = scale * (1.0f - p1) * 10.0f;
    g_wm4[idx] = make_float4(w0 * m0, m0, w1 * m1, m1);
  }
}

// ---------------------------------------------------------------------------
// Pass 1 (unchanged from R9): cp.async raw K/V ring -> transform -> MMA.
// ---------------------------------------------------------------------------
__global__ void __launch_bounds__(256, 2)
ma_pass1(const float* __restrict__ Kin, const float* __restrict__ Vin) {
  extern __shared__ uint32_t sm[];
  const int tid = threadIdx.x;
  const int bh = blockIdx.y;
  const int b = bh >> 4;
  const int chunk = blockIdx.x;
  const float* Kg = Kin + (size_t)bh * LLc * DDc;
  const float* Vg = Vin + (size_t)bh * LLc * DDc;
  const float4* Wg = g_wm4 + (size_t)b * (LLc / 2);

  const int warp = tid >> 5, lane = tid & 31;
  const int g = lane >> 2, t = lane & 3;
  const int q = lane >> 3, r8 = lane & 7;
  const int qh = q >> 1, ql = q & 1;
  const int mo = (warp & 3) * 32;    // d
  const int no = (warp >> 2) * 64;   // e

  uint32_t smb = (uint32_t)__cvta_generic_to_shared(sm);

  uint32_t aAddrHi[2];
#pragma unroll
  for (int mt = 0; mt < 2; ++mt) {
    int row = mo + mt * 16 + ql * 8 + r8;
    aAddrHi[mt] = smb + (uint32_t)(row * 32) +
                  (uint32_t)(((qh ^ ((row >> 2) & 1))) << 4);
  }
  uint32_t bAddrHi[4];
#pragma unroll
  for (int np = 0; np < 4; ++np) {
    int row = no + np * 16 + qh * 8 + r8;
    bAddrHi[np] = smb + 8192u + (uint32_t)(row * 32) +
                  (uint32_t)(((ql ^ ((row >> 2) & 1))) << 4);
  }

  const int dst = tid & 127;          // d (K) or e (V) row
  const int chk = tid >> 7;           // which 8-l chunk (0/1)
  const int schk = chk ^ ((dst >> 2) & 1);

  float C[2][8][4];
#pragma unroll
  for (int i = 0; i < 2; i++)
#pragma unroll
    for (int j = 0; j < 8; j++)
#pragma unroll
      for (int p = 0; p < 4; p++) C[i][j][p] = 0.0f;

  const int l0c = chunk * CLc;

  const int crow = tid >> 4;          // 0..15 (l within step)
  const int ccol = tid & 15;          // 0..15 (4-word chunk)
  auto cpKV = [&](int s) {
    uint32_t kb = smb + (uint32_t)(8192 + (s % 3) * 4096) * 4u;
    uint32_t vb = kb + 8192u;
    const float* kg = Kg + (size_t)(l0c + s * 16 + crow) * DDc + ccol * 4;
    const float* vg = Vg + (size_t)(l0c + s * 16 + crow) * DDc + ccol * 4;
    uint32_t so = (uint32_t)(crow * 128 + ccol * 4) * 4u;
    asm volatile("cp.async.cg.shared.global [%0], [%1], 16;\n"
                 :: "r"(kb + so), "l"(kg));
    asm volatile("cp.async.cg.shared.global [%0], [%1], 16;\n"
                 :: "r"(kb + so + 256u), "l"(kg + 64));
    asm volatile("cp.async.cg.shared.global [%0], [%1], 16;\n"
                 :: "r"(vb + so), "l"(vg));
    asm volatile("cp.async.cg.shared.global [%0], [%1], 16;\n"
                 :: "r"(vb + so + 256u), "l"(vg + 64));
    asm volatile("cp.async.commit_group;\n" ::: "memory");
  };

  auto transform = [&](int s) {
    const uint32_t* kb = sm + 8192 + (s % 3) * 4096;
    const uint32_t* vb = kb + 2048;
    int l = l0c + s * 16 + chk * 8;
    float4 w4[4];
#pragma unroll
    for (int i = 0; i < 4; ++i) w4[i] = Wg[(l >> 1) + i];
    float kf[8], vf[8];
#pragma unroll
    for (int i = 0; i < 4; ++i) {
      int rw = (chk * 8 + 2 * i) * 128 + dst;
      float k0 = __uint_as_float(kb[rw]);
      float k1 = __uint_as_float(kb[rw + 128]);
      float v0 = __uint_as_float(vb[rw]);
      float v1 = __uint_as_float(vb[rw + 128]);
      kf[2 * i] = elup(k0) * w4[i].x;
      kf[2 * i + 1] = elup(k1) * w4[i].z;
      vf[2 * i] = v0 * w4[i].y;
      vf[2 * i + 1] = v1 * w4[i].w;
    }
    uint4 khi, klo, vhi, vlo;
    split_pair(kf[0], kf[1], khi.x, klo.x);
    split_pair(kf[2], kf[3], khi.y, klo.y);
    split_pair(kf[4], kf[5], khi.z, klo.z);
    split_pair(kf[6], kf[7], khi.w, klo.w);
    split_pair(vf[0], vf[1], vhi.x, vlo.x);
    split_pair(vf[2], vf[3], vhi.y, vlo.y);
    split_pair(vf[4], vf[5], vhi.z, vlo.z);
    split_pair(vf[6], vf[7], vhi.w, vlo.w);
    int off = (s & 1) * 4096 + dst * 8 + (schk << 2);
    *reinterpret_cast<uint4*>(sm + off) = khi;
    *reinterpret_cast<uint4*>(sm + off + 1024) = klo;
    *reinterpret_cast<uint4*>(sm + off + 2048) = vhi;
    *reinterpret_cast<uint4*>(sm + off + 3072) = vlo;
  };

  auto mmastep = [&](int bsel) {
    const uint32_t bb = (uint32_t)bsel * 16384u;
    uint32_t Ahi[2][4], Alo[2][4];
#pragma unroll
    for (int mt = 0; mt < 2; ++mt) {
      ldsm_x4(Ahi[mt], aAddrHi[mt] + bb);
      ldsm_x4(Alo[mt], aAddrHi[mt] + bb + 4096u);
    }
#pragma unroll
    for (int np = 0; np < 4; ++np) {
      uint32_t Bh[4], Bl[4];
      ldsm_x4(Bh, bAddrHi[np] + bb);
      ldsm_x4(Bl, bAddrHi[np] + bb + 4096u);
#pragma unroll
      for (int mt = 0; mt < 2; ++mt) {
        mma_bf16(C[mt][2 * np], Ahi[mt], Bh);
        mma_bf16(C[mt][2 * np], Ahi[mt], Bl);
        mma_bf16(C[mt][2 * np], Alo[mt], Bh);
        mma_bf16(C[mt][2 * np + 1], Ahi[mt], Bh + 2);
        mma_bf16(C[mt][2 * np + 1], Ahi[mt], Bl + 2);
        mma_bf16(C[mt][2 * np + 1], Alo[mt], Bh + 2);
      }
    }
  };

  cpKV(0);
  cpKV(1);
  cpKV(2);
  asm volatile("cp.async.wait_group 2;\n" ::: "memory");
  __syncthreads();
  transform(0);
  asm volatile("cp.async.wait_group 1;\n" ::: "memory");
  __syncthreads();

#pragma unroll 1
  for (int s = 0; s < 32; ++s) {
    if (s < 29) cpKV(s + 3);
    mmastep(s & 1);
    if (s < 31) transform(s + 1);
    if (s < 29) {
      asm volatile("cp.async.wait_group 1;\n" ::: "memory");
    } else if (s == 29) {
      asm volatile("cp.async.wait_group 0;\n" ::: "memory");
    }
    __syncthreads();
  }

  float* out = g_KVp + (size_t)(chunk * BHc + bh) * DDc * DDc;
#pragma unroll
  for (int mt = 0; mt < 2; ++mt)
#pragma unroll
    for (int nt = 0; nt < 8; ++nt) {
      int d0 = mo + mt * 16 + g;
      int e0 = no + nt * 8 + t * 2;
      *reinterpret_cast<float2*>(out + (size_t)d0 * DDc + e0) =
          make_float2(C[mt][nt][0], C[mt][nt][1]);
      *reinterpret_cast<float2*>(out + (size_t)(d0 + 8) * DDc + e0) =
          make_float2(C[mt][nt][2], C[mt][nt][3]);
    }
}

// ---------------------------------------------------------------------------
__global__ void __launch_bounds__(128) ma_reduce() {
  const int e = threadIdx.x;
  const int bh = blockIdx.x >> 6;
  const int dp = blockIdx.x & 63;
  const int d = dp * 2;
  float a0 = 0.0f, a1 = 0.0f;
  for (int c = 0; c < CHUNKSc; ++c) {
    const float* p = g_KVp + (size_t)(c * BHc + bh) * DDc * DDc;
    a0 += p[(size_t)d * DDc + e];
    a1 += p[(size_t)(d + 1) * DDc + e];
  }
  uint32_t hi, lo;
  split_pair(a0, a1, hi, lo);
  g_KVThi[(size_t)bh * 8192 + e * 64 + dp] = hi;
  g_KVTlo[(size_t)bh * 8192 + e * 64 + dp] = lo;
}

// ---------------------------------------------------------------------------
// Pass 2 (e-split, warp-private Q ring): CTA = (128 l) x (bh, e-half of 64).
// B = KV^T e-half smem-resident (32 KB), staged once (single __syncthreads).
// Q: per-warp cp.async ring (3 bufs x 256 words/warp); warps fully decoupled
// in the main loop (wait_group + __syncwarp only, NO block barriers).
// Swizzle phys_chunk = c ^ (row&2) ^ ((row>>2)&1): conflict-free for the
// cp.async write phases and both LDS.64 read phases.
// smem words: BHI[0,4096) BLO[4096,8192) Q[8192, 8192+8*768)
// ---------------------------------------------------------------------------
#define QOFF 8192
#define QWBUF 768   // 3 * 256 words per warp

__global__ void __launch_bounds__(256, 3)
ma_pass2(const float* __restrict__ Qin, float* __restrict__ Xout, float scale) {
  extern __shared__ uint32_t sm[];

  const int tid = threadIdx.x;
  const int bh = blockIdx.y >> 1;
  const int eh = blockIdx.y & 1;
  const int l0 = blockIdx.x * 128;
  const float* Qg = Qin + (size_t)bh * LLc * DDc;
  float* Xg = Xout + (size_t)bh * LLc * DDc + eh * 64;

  const int warp = tid >> 5, lane = tid & 31;
  const int g = lane >> 2, t = lane & 3;
  const int q = lane >> 3, r8 = lane & 7;
  const int qh = q >> 1, ql = q & 1;
  const int lw = warp * 16;                 // warp's l offset

  uint32_t smb = (uint32_t)__cvta_generic_to_shared(sm);

  // ---- stage B e-half once (swizzled): 64 rows x 16 uint4 ----
  {
    const uint4* shi = reinterpret_cast<const uint4*>(
        g_KVThi + (size_t)bh * 8192 + (size_t)eh * 4096);
    const uint4* slo = reinterpret_cast<const uint4*>(
        g_KVTlo + (size_t)bh * 8192 + (size_t)eh * 4096);
#pragma unroll
    for (int i = 0; i < 4; ++i) {
      int idx4 = tid + i * 256;        // 0..1023
      int e = idx4 >> 4, c = idx4 & 15;
      int w = e * 64 + ((c ^ (e & 7)) << 2);
      *reinterpret_cast<uint4*>(sm + w) = shi[idx4];
      *reinterpret_cast<uint4*>(sm + 4096 + w) = slo[idx4];
    }
  }

  uint32_t bBhi[4], bBlo[4];
#pragma unroll
  for (int np = 0; np < 4; ++np) {
    int row = np * 16 + qh * 8 + r8;
    bBhi[np] = smb + (uint32_t)(row * 64) * 4u;
    bBlo[np] = smb + (4096u + (uint32_t)(row * 64)) * 4u;
  }

  // ---- per-warp Q ring ----
  const int qrow = lane & 15;           // local row this lane stages
  const int qc0 = (lane >> 4) * 2;      // chunks {0,1} or {2,3}
  const uint32_t qbase = smb + (uint32_t)(QOFF + warp * QWBUF) * 4u;
  const int qsw = (qrow & 2) ^ ((qrow >> 2) & 1);

  auto cpQ = [&](int kk) {
    uint32_t sb = qbase + (uint32_t)((kk % 3) * 256) * 4u;
    const float* gp = Qg + (size_t)(l0 + lw + qrow) * DDc + kk * 16;
#pragma unroll
    for (int c = qc0; c < qc0 + 2; ++c) {
      int pc = c ^ qsw;
      asm volatile("cp.async.cg.shared.global [%0], [%1], 16;\n"
                   :: "r"(sb + (uint32_t)(qrow * 16 + pc * 4) * 4u),
                      "l"(gp + c * 4));
    }
    asm volatile("cp.async.commit_group;\n" ::: "memory");
  };

  // logical word w of local row -> physical word offset within a Q buffer
  auto qword = [](int row, int w) {
    int s = (row & 2) ^ ((row >> 2) & 1);
    return row * 16 + ((((w >> 2) ^ s) & 3) << 2) + (w & 3);
  };

  float C[8][4];
#pragma unroll
  for (int j = 0; j < 8; j++)
#pragma unroll
    for (int p = 0; p < 4; p++) C[j][p] = 0.0f;

  cpQ(0);
  __syncthreads();   // B stage visible; only block barrier in the kernel

#pragma unroll 1
  for (int kk = 0; kk < 8; ++kk) {
    if (kk < 7) {
      cpQ(kk + 1);
      asm volatile("cp.async.wait_group 1;\n" ::: "memory");
    } else {
      asm volatile("cp.async.wait_group 0;\n" ::: "memory");
    }
    __syncwarp();

    const uint32_t* qb = sm + QOFF + warp * QWBUF + (kk % 3) * 256;
    float2 q00 = *reinterpret_cast<const float2*>(qb + qword(g, t * 2));
    float2 q01 = *reinterpret_cast<const float2*>(qb + qword(g, t * 2 + 8));
    float2 q10 = *reinterpret_cast<const float2*>(qb + qword(g + 8, t * 2));
    float2 q11 = *reinterpret_cast<const float2*>(qb + qword(g + 8, t * 2 + 8));

    uint32_t Ahi[4], Alo[4];
    split_pair(elup(q00.x) * scale, elup(q00.y) * scale, Ahi[0], Alo[0]);
    split_pair(elup(q10.x) * scale, elup(q10.y) * scale, Ahi[1], Alo[1]);
    split_pair(elup(q01.x) * scale, elup(q01.y) * scale, Ahi[2], Alo[2]);
    split_pair(elup(q11.x) * scale, elup(q11.y) * scale, Ahi[3], Alo[3]);

    int offB = (((kk * 2 + ql) ^ r8) << 4);
#pragma unroll
    for (int np = 0; np < 4; ++np) {
      uint32_t Bh[4], Bl[4];
      ldsm_x4(Bh, bBhi[np] + offB);
      ldsm_x4(Bl, bBlo[np] + offB);
      mma_bf16(C[2 * np], Ahi, Bh);
      mma_bf16(C[2 * np], Ahi, Bl);
      mma_bf16(C[2 * np], Alo, Bh);
      mma_bf16(C[2 * np + 1], Ahi, Bh + 2);
      mma_bf16(C[2 * np + 1], Ahi, Bl + 2);
      mma_bf16(C[2 * np + 1], Alo, Bh + 2);
    }
  }

  // ---- epilogue ----
#pragma unroll
  for (int nt = 0; nt < 8; ++nt) {
    int lr = l0 + lw + g;
    int e0 = nt * 8 + t * 2;
    *reinterpret_cast<float2*>(Xg + (size_t)lr * DDc + e0) =
        make_float2(C[nt][0], C[nt][1]);
    *reinterpret_cast<float2*>(Xg + (size_t)(lr + 8) * DDc + e0) =
        make_float2(C[nt][2], C[nt][3]);
  }
}

// ---------------------------------------------------------------------------
extern "C" void kernel_launch(void* const* d_in, const int* in_sizes, int n_in,
                              void* d_out, int out_size) {
  const float* Q = (const float*)d_in[0];
  const float* K = (const float*)d_in[1];
  const float* V = (const float*)d_in[2];
  const float* M = (const float*)d_in[3];
  float* X = (float*)d_out;
  (void)in_sizes; (void)n_in; (void)out_size;

  const float scale = powf((float)LLc, -0.25f);

  cudaFuncSetAttribute(ma_pass1, cudaFuncAttributeMaxDynamicSharedMemorySize,
                       (8192 + 3 * 4096) * 4);
  cudaFuncSetAttribute(ma_pass2, cudaFuncAttributeMaxDynamicSharedMemorySize,
                       (QOFF + 8 * QWBUF) * 4);

  ma_init<<<(LLc + 255) / 256, 256>>>(M, scale);
  dim3 g1(CHUNKSc, BHc);
  ma_pass1<<<g1, 256, (8192 + 3 * 4096) * 4>>>(K, V);
  ma_reduce<<<BHc * 64, 128>>>();
  dim3 g2(LLc / 128, BHc * 2);
  ma_pass2<<<g2, 256, (QOFF + 8 * QWBUF) * 4>>>(Q, X, scale);
}

// round 11
// speedup vs baseline: 2.2270x; 1.1374x over previous
#include <cuda_runtime.h>
#include <cuda_fp16.h>
#include <stdint.h>
#include <math.h>

// ---------------------------------------------------------------------------
// MomentumAttention (linear attention), fp16 2-term MMA (A single, B hi/lo):
//   Qf = (elu(Q)+1)*scale ; Kf = (elu(K)+1)*mask*scale*mw[l] ; Vf = V*mask
//   KV[d][e] = sum_l Kf[l][d]*Vf[l][e] ;  X = Qf @ KV
// Legacy mma.sync path (tcgen05 unavailable on this build target).
// ---------------------------------------------------------------------------

#define LLc 8192
#define DDc 128
#define BHc 32
#define CHUNKSc 16
#define CLc (LLc / CHUNKSc)   // 512

__device__ float    g_KVp[CHUNKSc * BHc * DDc * DDc];  // per-chunk partials
__device__ float4   g_wm4[2 * LLc / 2];                // {w*m, m, w*m, m} per l-pair
__device__ uint32_t g_KVThi[BHc * DDc * (DDc / 2)];    // [bh][e][d-pair] fp16x2
__device__ uint32_t g_KVTlo[BHc * DDc * (DDc / 2)];

__device__ __forceinline__ float elup(float x) {
  return x > 0.0f ? x + 1.0f : __expf(x);
}

__device__ __forceinline__ uint32_t pack_h2(float a, float b) {
  __half2 h = __floats2half2_rn(a, b);
  return *reinterpret_cast<uint32_t*>(&h);
}

__device__ __forceinline__ void split_pair_h(float a, float b,
                                             uint32_t& hi, uint32_t& lo) {
  __half2 h = __floats2half2_rn(a, b);
  hi = *reinterpret_cast<uint32_t*>(&h);
  float ra = a - __half2float(h.x);
  float rb = b - __half2float(h.y);
  __half2 l2 = __floats2half2_rn(ra, rb);
  lo = *reinterpret_cast<uint32_t*>(&l2);
}

__device__ __forceinline__ void mma_f16(float* c, const uint32_t* a,
                                        const uint32_t* b) {
  asm volatile(
      "mma.sync.aligned.m16n8k16.row.col.f32.f16.f16.f32 "
      "{%0,%1,%2,%3},{%4,%5,%6,%7},{%8,%9},{%0,%1,%2,%3};\n"
      : "+f"(c[0]), "+f"(c[1]), "+f"(c[2]), "+f"(c[3])
      : "r"(a[0]), "r"(a[1]), "r"(a[2]), "r"(a[3]), "r"(b[0]), "r"(b[1]));
}

__device__ __forceinline__ void ldsm_x4(uint32_t* r, uint32_t addr) {
  asm volatile(
      "ldmatrix.sync.aligned.m8n8.x4.shared.b16 {%0,%1,%2,%3}, [%4];"
      : "=r"(r[0]), "=r"(r[1]), "=r"(r[2]), "=r"(r[3])
      : "r"(addr));
}

// ---------------------------------------------------------------------------
__global__ void ma_init(const float* __restrict__ mask, float scale) {
  int idx = blockIdx.x * blockDim.x + threadIdx.x;   // 0 .. 8191
  if (idx < 2 * (LLc / 2)) {
    int b = idx >> 12;
    int l = (idx & 4095) * 2;
    float m0 = mask[b * LLc + l];
    float m1 = mask[b * LLc + l + 1];
    float p0 = powf(0.9f, (float)(LLc - l));
    float p1 = powf(0.9f, (float)(LLc - l - 1));
    float w0 = scale * (1.0f - p0) * 10.0f;
    float w1 = scale * (1.0f - p1) * 10.0f;
    g_wm4[idx] = make_float4(w0 * m0, m0, w1 * m1, m1);
  }
}

// ---------------------------------------------------------------------------
// Pass 1: C[d][e] += sum_l Kf[l][d]*Vf[l][e].  A = Kf single fp16, B = Vf
// fp16 hi/lo -> 2 MMAs per k16. cp.async raw K/V ring (3 bufs of 16 l) feeds
// transform -> fp16 double buffer. One sync per step.
// smem (words): fp16 buffers: buf b at b*3072 {KH +0, VHI +1024, VLO +2048};
//               raw ring at 6144 + (s%3)*4096 {rawK +0, rawV +2048}.
// 8 warps, warp tile 32(d) x 64(e).
// ---------------------------------------------------------------------------
__global__ void __launch_bounds__(256, 2)
ma_pass1(const float* __restrict__ Kin, const float* __restrict__ Vin) {
  extern __shared__ uint32_t sm[];
  const int tid = threadIdx.x;
  const int bh = blockIdx.y;
  const int b = bh >> 4;
  const int chunk = blockIdx.x;
  const float* Kg = Kin + (size_t)bh * LLc * DDc;
  const float* Vg = Vin + (size_t)bh * LLc * DDc;
  const float4* Wg = g_wm4 + (size_t)b * (LLc / 2);

  const int warp = tid >> 5, lane = tid & 31;
  const int g = lane >> 2, t = lane & 3;
  const int q = lane >> 3, r8 = lane & 7;
  const int qh = q >> 1, ql = q & 1;
  const int mo = (warp & 3) * 32;    // d
  const int no = (warp >> 2) * 64;   // e

  uint32_t smb = (uint32_t)__cvta_generic_to_shared(sm);

  // fragment addresses (byte offsets within fp16 buffer 0); buffer stride 12288B
  uint32_t aAddr[2];
#pragma unroll
  for (int mt = 0; mt < 2; ++mt) {
    int row = mo + mt * 16 + ql * 8 + r8;
    aAddr[mt] = smb + (uint32_t)(row * 32) +
                (uint32_t)(((qh ^ ((row >> 2) & 1))) << 4);
  }
  uint32_t bAddr[4];
#pragma unroll
  for (int np = 0; np < 4; ++np) {
    int row = no + np * 16 + qh * 8 + r8;
    bAddr[np] = smb + 4096u + (uint32_t)(row * 32) +
                (uint32_t)(((ql ^ ((row >> 2) & 1))) << 4);
  }

  const int dst = tid & 127;          // d (K) or e (V) row
  const int chk = tid >> 7;           // which 8-l chunk (0/1)
  const int schk = chk ^ ((dst >> 2) & 1);

  float C[2][8][4];
#pragma unroll
  for (int i = 0; i < 2; i++)
#pragma unroll
    for (int j = 0; j < 8; j++)
#pragma unroll
      for (int p = 0; p < 4; p++) C[i][j][p] = 0.0f;

  const int l0c = chunk * CLc;

  const int crow = tid >> 4;          // 0..15 (l within step)
  const int ccol = tid & 15;          // 0..15 (4-word chunk)
  auto cpKV = [&](int s) {
    uint32_t kb = smb + (uint32_t)(6144 + (s % 3) * 4096) * 4u;
    uint32_t vb = kb + 8192u;
    const float* kg = Kg + (size_t)(l0c + s * 16 + crow) * DDc + ccol * 4;
    const float* vg = Vg + (size_t)(l0c + s * 16 + crow) * DDc + ccol * 4;
    uint32_t so = (uint32_t)(crow * 128 + ccol * 4) * 4u;
    asm volatile("cp.async.cg.shared.global [%0], [%1], 16;\n"
                 :: "r"(kb + so), "l"(kg));
    asm volatile("cp.async.cg.shared.global [%0], [%1], 16;\n"
                 :: "r"(kb + so + 256u), "l"(kg + 64));
    asm volatile("cp.async.cg.shared.global [%0], [%1], 16;\n"
                 :: "r"(vb + so), "l"(vg));
    asm volatile("cp.async.cg.shared.global [%0], [%1], 16;\n"
                 :: "r"(vb + so + 256u), "l"(vg + 64));
    asm volatile("cp.async.commit_group;\n" ::: "memory");
  };

  auto transform = [&](int s) {
    const uint32_t* kb = sm + 6144 + (s % 3) * 4096;
    const uint32_t* vb = kb + 2048;
    int l = l0c + s * 16 + chk * 8;
    float4 w4[4];
#pragma unroll
    for (int i = 0; i < 4; ++i) w4[i] = Wg[(l >> 1) + i];
    float kf[8], vf[8];
#pragma unroll
    for (int i = 0; i < 4; ++i) {
      int rw = (chk * 8 + 2 * i) * 128 + dst;
      float k0 = __uint_as_float(kb[rw]);
      float k1 = __uint_as_float(kb[rw + 128]);
      float v0 = __uint_as_float(vb[rw]);
      float v1 = __uint_as_float(vb[rw + 128]);
      kf[2 * i] = elup(k0) * w4[i].x;
      kf[2 * i + 1] = elup(k1) * w4[i].z;
      vf[2 * i] = v0 * w4[i].y;
      vf[2 * i + 1] = v1 * w4[i].w;
    }
    uint4 kh, vhi, vlo;
    kh.x = pack_h2(kf[0], kf[1]);
    kh.y = pack_h2(kf[2], kf[3]);
    kh.z = pack_h2(kf[4], kf[5]);
    kh.w = pack_h2(kf[6], kf[7]);
    split_pair_h(vf[0], vf[1], vhi.x, vlo.x);
    split_pair_h(vf[2], vf[3], vhi.y, vlo.y);
    split_pair_h(vf[4], vf[5], vhi.z, vlo.z);
    split_pair_h(vf[6], vf[7], vhi.w, vlo.w);
    int off = (s & 1) * 3072 + dst * 8 + (schk << 2);
    *reinterpret_cast<uint4*>(sm + off) = kh;
    *reinterpret_cast<uint4*>(sm + off + 1024) = vhi;
    *reinterpret_cast<uint4*>(sm + off + 2048) = vlo;
  };

  auto mmastep = [&](int bsel) {
    const uint32_t bb = (uint32_t)bsel * 12288u;
    uint32_t A[2][4];
#pragma unroll
    for (int mt = 0; mt < 2; ++mt) ldsm_x4(A[mt], aAddr[mt] + bb);
#pragma unroll
    for (int np = 0; np < 4; ++np) {
      uint32_t Bh[4], Bl[4];
      ldsm_x4(Bh, bAddr[np] + bb);
      ldsm_x4(Bl, bAddr[np] + bb + 4096u);
#pragma unroll
      for (int mt = 0; mt < 2; ++mt) {
        mma_f16(C[mt][2 * np], A[mt], Bh);
        mma_f16(C[mt][2 * np], A[mt], Bl);
        mma_f16(C[mt][2 * np + 1], A[mt], Bh + 2);
        mma_f16(C[mt][2 * np + 1], A[mt], Bl + 2);
      }
    }
  };

  cpKV(0);
  cpKV(1);
  cpKV(2);
  asm volatile("cp.async.wait_group 2;\n" ::: "memory");
  __syncthreads();
  transform(0);
  asm volatile("cp.async.wait_group 1;\n" ::: "memory");
  __syncthreads();

#pragma unroll 1
  for (int s = 0; s < 32; ++s) {
    if (s < 29) cpKV(s + 3);
    mmastep(s & 1);
    if (s < 31) transform(s + 1);
    if (s < 29) {
      asm volatile("cp.async.wait_group 1;\n" ::: "memory");
    } else if (s == 29) {
      asm volatile("cp.async.wait_group 0;\n" ::: "memory");
    }
    __syncthreads();
  }

  float* out = g_KVp + (size_t)(chunk * BHc + bh) * DDc * DDc;
#pragma unroll
  for (int mt = 0; mt < 2; ++mt)
#pragma unroll
    for (int nt = 0; nt < 8; ++nt) {
      int d0 = mo + mt * 16 + g;
      int e0 = no + nt * 8 + t * 2;
      *reinterpret_cast<float2*>(out + (size_t)d0 * DDc + e0) =
          make_float2(C[mt][nt][0], C[mt][nt][1]);
      *reinterpret_cast<float2*>(out + (size_t)(d0 + 8) * DDc + e0) =
          make_float2(C[mt][nt][2], C[mt][nt][3]);
    }
}

// ---------------------------------------------------------------------------
__global__ void __launch_bounds__(128) ma_reduce() {
  const int e = threadIdx.x;
  const int bh = blockIdx.x >> 6;
  const int dp = blockIdx.x & 63;
  const int d = dp * 2;
  float a0 = 0.0f, a1 = 0.0f;
  for (int c = 0; c < CHUNKSc; ++c) {
    const float* p = g_KVp + (size_t)(c * BHc + bh) * DDc * DDc;
    a0 += p[(size_t)d * DDc + e];
    a1 += p[(size_t)(d + 1) * DDc + e];
  }
  uint32_t hi, lo;
  split_pair_h(a0, a1, hi, lo);
  g_KVThi[(size_t)bh * 8192 + e * 64 + dp] = hi;
  g_KVTlo[(size_t)bh * 8192 + e * 64 + dp] = lo;
}

// ---------------------------------------------------------------------------
// Pass 2 (e-split, warp-private Q ring): CTA = (128 l) x (bh, e-half of 64).
// A = Qf single fp16 (computed in regs), B = KVT fp16 hi/lo -> 2 MMAs/k16.
// B e-half smem-resident (32 KB); Q per-warp cp.async ring, no block barriers
// in the main loop.
// smem words: BHI[0,4096) BLO[4096,8192) Q[8192, 8192+8*768)
// ---------------------------------------------------------------------------
#define QOFF 8192
#define QWBUF 768   // 3 * 256 words per warp

__global__ void __launch_bounds__(256, 3)
ma_pass2(const float* __restrict__ Qin, float* __restrict__ Xout, float scale) {
  extern __shared__ uint32_t sm[];

  const int tid = threadIdx.x;
  const int bh = blockIdx.y >> 1;
  const int eh = blockIdx.y & 1;
  const int l0 = blockIdx.x * 128;
  const float* Qg = Qin + (size_t)bh * LLc * DDc;
  float* Xg = Xout + (size_t)bh * LLc * DDc + eh * 64;

  const int warp = tid >> 5, lane = tid & 31;
  const int g = lane >> 2, t = lane & 3;
  const int q = lane >> 3, r8 = lane & 7;
  const int qh = q >> 1, ql = q & 1;
  const int lw = warp * 16;                 // warp's l offset

  uint32_t smb = (uint32_t)__cvta_generic_to_shared(sm);

  // ---- stage B e-half once (swizzled): 64 rows x 16 uint4 ----
  {
    const uint4* shi = reinterpret_cast<const uint4*>(
        g_KVThi + (size_t)bh * 8192 + (size_t)eh * 4096);
    const uint4* slo = reinterpret_cast<const uint4*>(
        g_KVTlo + (size_t)bh * 8192 + (size_t)eh * 4096);
#pragma unroll
    for (int i = 0; i < 4; ++i) {
      int idx4 = tid + i * 256;        // 0..1023
      int e = idx4 >> 4, c = idx4 & 15;
      int w = e * 64 + ((c ^ (e & 7)) << 2);
      *reinterpret_cast<uint4*>(sm + w) = shi[idx4];
      *reinterpret_cast<uint4*>(sm + 4096 + w) = slo[idx4];
    }
  }

  uint32_t bBhi[4], bBlo[4];
#pragma unroll
  for (int np = 0; np < 4; ++np) {
    int row = np * 16 + qh * 8 + r8;
    bBhi[np] = smb + (uint32_t)(row * 64) * 4u;
    bBlo[np] = smb + (4096u + (uint32_t)(row * 64)) * 4u;
  }

  // ---- per-warp Q ring ----
  const int qrow = lane & 15;           // local row this lane stages
  const int qc0 = (lane >> 4) * 2;      // chunks {0,1} or {2,3}
  const uint32_t qbase = smb + (uint32_t)(QOFF + warp * QWBUF) * 4u;
  const int qsw = (qrow & 2) ^ ((qrow >> 2) & 1);

  auto cpQ = [&](int kk) {
    uint32_t sb = qbase + (uint32_t)((kk % 3) * 256) * 4u;
    const float* gp = Qg + (size_t)(l0 + lw + qrow) * DDc + kk * 16;
#pragma unroll
    for (int c = qc0; c < qc0 + 2; ++c) {
      int pc = c ^ qsw;
      asm volatile("cp.async.cg.shared.global [%0], [%1], 16;\n"
                   :: "r"(sb + (uint32_t)(qrow * 16 + pc * 4) * 4u),
                      "l"(gp + c * 4));
    }
    asm volatile("cp.async.commit_group;\n" ::: "memory");
  };

  auto qword = [](int row, int w) {
    int s = (row & 2) ^ ((row >> 2) & 1);
    return row * 16 + ((((w >> 2) ^ s) & 3) << 2) + (w & 3);
  };

  float C[8][4];
#pragma unroll
  for (int j = 0; j < 8; j++)
#pragma unroll
    for (int p = 0; p < 4; p++) C[j][p] = 0.0f;

  cpQ(0);
  __syncthreads();   // B stage visible; only block barrier in the kernel

#pragma unroll 1
  for (int kk = 0; kk < 8; ++kk) {
    if (kk < 7) {
      cpQ(kk + 1);
      asm volatile("cp.async.wait_group 1;\n" ::: "memory");
    } else {
      asm volatile("cp.async.wait_group 0;\n" ::: "memory");
    }
    __syncwarp();

    const uint32_t* qb = sm + QOFF + warp * QWBUF + (kk % 3) * 256;
    float2 q00 = *reinterpret_cast<const float2*>(qb + qword(g, t * 2));
    float2 q01 = *reinterpret_cast<const float2*>(qb + qword(g, t * 2 + 8));
    float2 q10 = *reinterpret_cast<const float2*>(qb + qword(g + 8, t * 2));
    float2 q11 = *reinterpret_cast<const float2*>(qb + qword(g + 8, t * 2 + 8));

    uint32_t A[4];
    A[0] = pack_h2(elup(q00.x) * scale, elup(q00.y) * scale);
    A[1] = pack_h2(elup(q10.x) * scale, elup(q10.y) * scale);
    A[2] = pack_h2(elup(q01.x) * scale, elup(q01.y) * scale);
    A[3] = pack_h2(elup(q11.x) * scale, elup(q11.y) * scale);

    int offB = (((kk * 2 + ql) ^ r8) << 4);
#pragma unroll
    for (int np = 0; np < 4; ++np) {
      uint32_t Bh[4], Bl[4];
      ldsm_x4(Bh, bBhi[np] + offB);
      ldsm_x4(Bl, bBlo[np] + offB);
      mma_f16(C[2 * np], A, Bh);
      mma_f16(C[2 * np], A, Bl);
      mma_f16(C[2 * np + 1], A, Bh + 2);
      mma_f16(C[2 * np + 1], A, Bl + 2);
    }
  }

  // ---- epilogue ----
#pragma unroll
  for (int nt = 0; nt < 8; ++nt) {
    int lr = l0 + lw + g;
    int e0 = nt * 8 + t * 2;
    *reinterpret_cast<float2*>(Xg + (size_t)lr * DDc + e0) =
        make_float2(C[nt][0], C[nt][1]);
    *reinterpret_cast<float2*>(Xg + (size_t)(lr + 8) * DDc + e0) =
        make_float2(C[nt][2], C[nt][3]);
  }
}

// ---------------------------------------------------------------------------
extern "C" void kernel_launch(void* const* d_in, const int* in_sizes, int n_in,
                              void* d_out, int out_size) {
  const float* Q = (const float*)d_in[0];
  const float* K = (const float*)d_in[1];
  const float* V = (const float*)d_in[2];
  const float* M = (const float*)d_in[3];
  float* X = (float*)d_out;
  (void)in_sizes; (void)n_in; (void)out_size;

  const float scale = powf((float)LLc, -0.25f);

  cudaFuncSetAttribute(ma_pass1, cudaFuncAttributeMaxDynamicSharedMemorySize,
                       (6144 + 3 * 4096) * 4);
  cudaFuncSetAttribute(ma_pass2, cudaFuncAttributeMaxDynamicSharedMemorySize,
                       (QOFF + 8 * QWBUF) * 4);

  ma_init<<<(LLc + 255) / 256, 256>>>(M, scale);
  dim3 g1(CHUNKSc, BHc);
  ma_pass1<<<g1, 256, (6144 + 3 * 4096) * 4>>>(K, V);
  ma_reduce<<<BHc * 64, 128>>>();
  dim3 g2(LLc / 128, BHc * 2);
  ma_pass2<<<g2, 256, (QOFF + 8 * QWBUF) * 4>>>(Q, X, scale);
}